// round 1
// baseline (speedup 1.0000x reference)
#include <cuda_runtime.h>

#define Bsz 16
#define HW 16384          // H*W per batch
#define Cdim 128
#define QKVN 384
#define NHEADS 4
#define HDp 32
#define SHIFT 4
#define EPSLN 1e-3f
#define SCALEQ 0.17677669529663689f
#define M_TOTAL (Bsz * HW)   // 262144 rows

// ---- scratch (static device globals; no runtime allocation) ----
__device__ float g_qkv[(size_t)M_TOTAL * QKVN];   // ~402 MB
__device__ float g_att[(size_t)M_TOTAL * Cdim];   // ~134 MB

// row m (window-ordered) -> source/dest token index in (B, H*W) layout
__device__ __forceinline__ int win_row_to_token(int m) {
    int b   = m >> 14;          // 16384 rows per batch
    int r   = m & 16383;
    int win = r >> 6;
    int n   = r & 63;
    int hb  = win >> 4;         // 16 window cols
    int wb  = win & 15;
    int h   = ((hb << 3) + (n >> 3) + SHIFT) & 127;
    int w   = ((wb << 3) + (n & 7) + SHIFT) & 127;
    return (b << 14) + (h << 7) + w;
}

// ============================================================
// Kernel A: QKV GEMM with shifted-window gather on A rows.
// Tile 128(M) x 64(N), K chunks of 16. 256 threads, 8x4 microtile.
// ============================================================
__global__ __launch_bounds__(256) void qkv_kernel(
    const float* __restrict__ x, const float* __restrict__ w,
    const float* __restrict__ bias) {
    __shared__ float As[128][17];
    __shared__ float Bs[16][68];
    const int tid   = threadIdx.x;
    const int mbase = blockIdx.y << 7;
    const int nbase = blockIdx.x << 6;
    const int ty    = tid >> 4;    // 0..15 (8-row groups)
    const int tx    = tid & 15;    // 0..15 (4-col groups)

    const int lr = tid >> 1;             // A-load row 0..127
    const int k8 = (tid & 1) << 3;       // 0 or 8
    const float* arow = x + (size_t)win_row_to_token(mbase + lr) * Cdim;

    const int kb = tid >> 4;             // B-load row 0..15
    const int n4 = (tid & 15) << 2;

    float acc[8][4];
#pragma unroll
    for (int i = 0; i < 8; i++)
#pragma unroll
        for (int j = 0; j < 4; j++) acc[i][j] = 0.f;

    for (int kc = 0; kc < 128; kc += 16) {
        float4 a0 = *(const float4*)(arow + kc + k8);
        float4 a1 = *(const float4*)(arow + kc + k8 + 4);
        As[lr][k8 + 0] = a0.x; As[lr][k8 + 1] = a0.y;
        As[lr][k8 + 2] = a0.z; As[lr][k8 + 3] = a0.w;
        As[lr][k8 + 4] = a1.x; As[lr][k8 + 5] = a1.y;
        As[lr][k8 + 6] = a1.z; As[lr][k8 + 7] = a1.w;
        *(float4*)&Bs[kb][n4] =
            *(const float4*)(w + (size_t)(kc + kb) * QKVN + nbase + n4);
        __syncthreads();
#pragma unroll
        for (int k = 0; k < 16; k++) {
            float4 bb = *(float4*)&Bs[k][tx << 2];
#pragma unroll
            for (int i = 0; i < 8; i++) {
                float a = As[(ty << 3) + i][k];
                acc[i][0] = fmaf(a, bb.x, acc[i][0]);
                acc[i][1] = fmaf(a, bb.y, acc[i][1]);
                acc[i][2] = fmaf(a, bb.z, acc[i][2]);
                acc[i][3] = fmaf(a, bb.w, acc[i][3]);
            }
        }
        __syncthreads();
    }
    float4 bv = *(const float4*)(bias + nbase + (tx << 2));
#pragma unroll
    for (int i = 0; i < 8; i++) {
        float4 o = make_float4(acc[i][0] + bv.x, acc[i][1] + bv.y,
                               acc[i][2] + bv.z, acc[i][3] + bv.w);
        *(float4*)&g_qkv[(size_t)(mbase + (ty << 3) + i) * QKVN + nbase + (tx << 2)] = o;
    }
}

// ============================================================
// Kernel B: windowed attention. One block per (window, head), 128 threads.
// ============================================================
__global__ __launch_bounds__(128) void attn_kernel(
    const float* __restrict__ bias_table, const int* __restrict__ rel_index,
    const float* __restrict__ mask) {
    __shared__ float qs[64][33], ks[64][33], vs[64][33];
    __shared__ float at[64][65];
    const int win  = blockIdx.x;
    const int head = blockIdx.y;
    const int wimg = win & 255;
    const int tid  = threadIdx.x;

    const float* base = g_qkv + (size_t)win * 64 * QKVN + head * HDp;
    for (int idx = tid; idx < 64 * 32; idx += 128) {
        int n = idx >> 5, d = idx & 31;
        const float* p = base + (size_t)n * QKVN + d;
        qs[n][d] = p[0] * SCALEQ;
        ks[n][d] = p[128];
        vs[n][d] = p[256];
    }
    __syncthreads();

    for (int idx = tid; idx < 4096; idx += 128) {
        int n = idx >> 6, mcol = idx & 63;
        float s = 0.f;
#pragma unroll
        for (int d = 0; d < 32; d++) s = fmaf(qs[n][d], ks[mcol][d], s);
        s += bias_table[rel_index[idx] * NHEADS + head];
        s += mask[(size_t)wimg * 4096 + idx];
        at[n][mcol] = s;
    }
    __syncthreads();

    {   // softmax: 2 threads per row
        int row = tid >> 1, half = tid & 1;
        int m0 = half << 5;
        float mx = -1e30f;
        for (int m = m0; m < m0 + 32; m++) mx = fmaxf(mx, at[row][m]);
        mx = fmaxf(mx, __shfl_xor_sync(0xffffffffu, mx, 1));
        float s = 0.f;
        for (int m = m0; m < m0 + 32; m++) {
            float e = __expf(at[row][m] - mx);
            at[row][m] = e;
            s += e;
        }
        s += __shfl_xor_sync(0xffffffffu, s, 1);
        float inv = 1.0f / s;
        for (int m = m0; m < m0 + 32; m++) at[row][m] *= inv;
    }
    __syncthreads();

    for (int idx = tid; idx < 2048; idx += 128) {
        int n = idx >> 5, d = idx & 31;
        float s = 0.f;
#pragma unroll
        for (int m = 0; m < 64; m++) s = fmaf(at[n][m], vs[m][d], s);
        g_att[((size_t)win * 64 + n) * Cdim + head * HDp + d] = s;
    }
}

// ============================================================
// Kernel C: proj GEMM + window-reverse/unshift + LayerNorm + residual.
// 64-row blocks, 256 threads, 8x4 microtile. Writes x1 into `out`.
// smem: w_proj(128x128) + A(64x128) = 96 KB dynamic.
// ============================================================
__global__ __launch_bounds__(256) void proj_kernel(
    const float* __restrict__ x, const float* __restrict__ wp_g,
    const float* __restrict__ bp, const float* __restrict__ g1,
    const float* __restrict__ be1, float* __restrict__ out) {
    extern __shared__ float sm[];
    float* wp = sm;             // 128*128
    float* As = sm + 16384;     // 64*128
    const int tid = threadIdx.x;
    const int mbase = blockIdx.x << 6;

    for (int i = tid; i < 4096; i += 256) {
        int k = i >> 5, n4 = (i & 31) << 2;
        *(float4*)&wp[k * 128 + n4] = *(const float4*)(wp_g + k * 128 + n4);
    }
    for (int i = tid; i < 2048; i += 256) {
        int r = i >> 5, n4 = (i & 31) << 2;
        *(float4*)&As[r * 128 + n4] =
            *(const float4*)(g_att + ((size_t)(mbase + r)) * Cdim + n4);
    }
    __syncthreads();

    const int ty = tid >> 5, tx = tid & 31;
    float acc[8][4];
#pragma unroll
    for (int i = 0; i < 8; i++)
#pragma unroll
        for (int j = 0; j < 4; j++) acc[i][j] = 0.f;

#pragma unroll 4
    for (int k = 0; k < 128; k++) {
        float4 bb = *(float4*)&wp[k * 128 + (tx << 2)];
#pragma unroll
        for (int i = 0; i < 8; i++) {
            float a = As[((ty << 3) + i) * 128 + k];
            acc[i][0] = fmaf(a, bb.x, acc[i][0]);
            acc[i][1] = fmaf(a, bb.y, acc[i][1]);
            acc[i][2] = fmaf(a, bb.z, acc[i][2]);
            acc[i][3] = fmaf(a, bb.w, acc[i][3]);
        }
    }

    float4 bp4  = *(const float4*)(bp  + (tx << 2));
    float4 g14  = *(const float4*)(g1  + (tx << 2));
    float4 be14 = *(const float4*)(be1 + (tx << 2));
#pragma unroll
    for (int i = 0; i < 8; i++) {
        float v0 = acc[i][0] + bp4.x, v1 = acc[i][1] + bp4.y;
        float v2 = acc[i][2] + bp4.z, v3 = acc[i][3] + bp4.w;
        float s = v0 + v1 + v2 + v3;
#pragma unroll
        for (int o = 16; o > 0; o >>= 1) s += __shfl_xor_sync(0xffffffffu, s, o);
        float mean = s * (1.0f / 128.0f);
        float d0 = v0 - mean, d1 = v1 - mean, d2 = v2 - mean, d3 = v3 - mean;
        float q = d0 * d0 + d1 * d1 + d2 * d2 + d3 * d3;
#pragma unroll
        for (int o = 16; o > 0; o >>= 1) q += __shfl_xor_sync(0xffffffffu, q, o);
        float rs = rsqrtf(q * (1.0f / 128.0f) + EPSLN);

        int tok = win_row_to_token(mbase + (ty << 3) + i);
        size_t off = (size_t)tok * Cdim + (tx << 2);
        float4 xr = *(const float4*)(x + off);
        float4 o4;
        o4.x = xr.x + d0 * rs * g14.x + be14.x;
        o4.y = xr.y + d1 * rs * g14.y + be14.y;
        o4.z = xr.z + d2 * rs * g14.z + be14.z;
        o4.w = xr.w + d3 * rs * g14.w + be14.w;
        *(float4*)(out + off) = o4;
    }
}

// ============================================================
// Kernel D: fused MLP fc1+GELU+fc2 (HID chunked by 128) + LN + residual.
// 64-row blocks, 256 threads. In-place on io (x1 -> final).
// smem: w1(64K)+w2(64K)+A(32K)+H(32K) = 192 KB dynamic.
// ============================================================
__global__ __launch_bounds__(256) void mlp_kernel(
    const float* __restrict__ w1g, const float* __restrict__ b1,
    const float* __restrict__ w2g, const float* __restrict__ b2,
    const float* __restrict__ g2, const float* __restrict__ be2,
    float* __restrict__ io) {
    extern __shared__ float sm[];
    float* w1 = sm;               // 128*128
    float* w2 = sm + 16384;       // 128*128
    float* As = sm + 32768;       // 64*128 (x1 tile)
    float* Hs = sm + 40960;       // 64*128
    const int tid = threadIdx.x;
    const int ty = tid >> 5, tx = tid & 31;
    const int mbase = blockIdx.x << 6;

    for (int i = tid; i < 2048; i += 256) {
        int r = i >> 5, n4 = (i & 31) << 2;
        *(float4*)&As[r * 128 + n4] =
            *(const float4*)(io + ((size_t)(mbase + r)) * Cdim + n4);
    }

    float acc[8][4];
#pragma unroll
    for (int i = 0; i < 8; i++)
#pragma unroll
        for (int j = 0; j < 4; j++) acc[i][j] = 0.f;

    for (int c = 0; c < 4; c++) {
        __syncthreads();   // prev-iter consumers done (also covers As load at c=0... completed below)
        for (int i = tid; i < 4096; i += 256) {
            int k = i >> 5, n4 = (i & 31) << 2;
            *(float4*)&w1[k * 128 + n4] =
                *(const float4*)(w1g + (size_t)k * 512 + (c << 7) + n4);
            *(float4*)&w2[k * 128 + n4] =
                *(const float4*)(w2g + ((size_t)((c << 7) + k)) * 128 + n4);
        }
        __syncthreads();

        float h[8][4];
#pragma unroll
        for (int i = 0; i < 8; i++)
#pragma unroll
            for (int j = 0; j < 4; j++) h[i][j] = 0.f;
#pragma unroll 4
        for (int k = 0; k < 128; k++) {
            float4 bb = *(float4*)&w1[k * 128 + (tx << 2)];
#pragma unroll
            for (int i = 0; i < 8; i++) {
                float a = As[((ty << 3) + i) * 128 + k];
                h[i][0] = fmaf(a, bb.x, h[i][0]);
                h[i][1] = fmaf(a, bb.y, h[i][1]);
                h[i][2] = fmaf(a, bb.z, h[i][2]);
                h[i][3] = fmaf(a, bb.w, h[i][3]);
            }
        }
        float4 b14 = *(const float4*)(b1 + (c << 7) + (tx << 2));
#pragma unroll
        for (int i = 0; i < 8; i++) {
            float hv[4] = {h[i][0] + b14.x, h[i][1] + b14.y,
                           h[i][2] + b14.z, h[i][3] + b14.w};
#pragma unroll
            for (int j = 0; j < 4; j++) {
                float v = hv[j];
                v = 0.5f * v * (1.0f + erff(v * 0.70710678118654752f));
                Hs[((ty << 3) + i) * 128 + (tx << 2) + j] = v;
            }
        }
        __syncthreads();
#pragma unroll 4
        for (int k = 0; k < 128; k++) {
            float4 bb = *(float4*)&w2[k * 128 + (tx << 2)];
#pragma unroll
            for (int i = 0; i < 8; i++) {
                float a = Hs[((ty << 3) + i) * 128 + k];
                acc[i][0] = fmaf(a, bb.x, acc[i][0]);
                acc[i][1] = fmaf(a, bb.y, acc[i][1]);
                acc[i][2] = fmaf(a, bb.z, acc[i][2]);
                acc[i][3] = fmaf(a, bb.w, acc[i][3]);
            }
        }
    }

    float4 b24  = *(const float4*)(b2  + (tx << 2));
    float4 g24  = *(const float4*)(g2  + (tx << 2));
    float4 be24 = *(const float4*)(be2 + (tx << 2));
#pragma unroll
    for (int i = 0; i < 8; i++) {
        float v0 = acc[i][0] + b24.x, v1 = acc[i][1] + b24.y;
        float v2 = acc[i][2] + b24.z, v3 = acc[i][3] + b24.w;
        float s = v0 + v1 + v2 + v3;
#pragma unroll
        for (int o = 16; o > 0; o >>= 1) s += __shfl_xor_sync(0xffffffffu, s, o);
        float mean = s * (1.0f / 128.0f);
        float d0 = v0 - mean, d1 = v1 - mean, d2 = v2 - mean, d3 = v3 - mean;
        float q = d0 * d0 + d1 * d1 + d2 * d2 + d3 * d3;
#pragma unroll
        for (int o = 16; o > 0; o >>= 1) q += __shfl_xor_sync(0xffffffffu, q, o);
        float rs = rsqrtf(q * (1.0f / 128.0f) + EPSLN);

        int rloc = (ty << 3) + i;
        float x0 = As[rloc * 128 + (tx << 2) + 0];
        float x1v = As[rloc * 128 + (tx << 2) + 1];
        float x2 = As[rloc * 128 + (tx << 2) + 2];
        float x3 = As[rloc * 128 + (tx << 2) + 3];
        float4 o4;
        o4.x = x0  + d0 * rs * g24.x + be24.x;
        o4.y = x1v + d1 * rs * g24.y + be24.y;
        o4.z = x2  + d2 * rs * g24.z + be24.z;
        o4.w = x3  + d3 * rs * g24.w + be24.w;
        *(float4*)(io + ((size_t)(mbase + rloc)) * Cdim + (tx << 2)) = o4;
    }
}

// ============================================================
extern "C" void kernel_launch(void* const* d_in, const int* in_sizes, int n_in,
                              void* d_out, int out_size) {
    const float* x          = (const float*)d_in[0];
    const float* w_qkv      = (const float*)d_in[1];
    const float* b_qkv      = (const float*)d_in[2];
    const float* bias_table = (const float*)d_in[3];
    const float* w_proj     = (const float*)d_in[4];
    const float* b_proj     = (const float*)d_in[5];
    const float* g1         = (const float*)d_in[6];
    const float* be1        = (const float*)d_in[7];
    const float* w_fc1      = (const float*)d_in[8];
    const float* b_fc1      = (const float*)d_in[9];
    const float* w_fc2      = (const float*)d_in[10];
    const float* b_fc2      = (const float*)d_in[11];
    const float* g2         = (const float*)d_in[12];
    const float* be2        = (const float*)d_in[13];
    const int*   rel_index  = (const int*)d_in[14];
    const float* attn_mask  = (const float*)d_in[15];
    float* out = (float*)d_out;

    cudaFuncSetAttribute(proj_kernel, cudaFuncAttributeMaxDynamicSharedMemorySize,
                         (16384 + 8192) * 4);
    cudaFuncSetAttribute(mlp_kernel, cudaFuncAttributeMaxDynamicSharedMemorySize,
                         (16384 * 2 + 8192 * 2) * 4);

    qkv_kernel<<<dim3(6, M_TOTAL / 128), 256>>>(x, w_qkv, b_qkv);
    attn_kernel<<<dim3(4096, 4), 128>>>(bias_table, rel_index, attn_mask);
    proj_kernel<<<M_TOTAL / 64, 256, (16384 + 8192) * 4>>>(x, w_proj, b_proj, g1, be1, out);
    mlp_kernel<<<M_TOTAL / 64, 256, (16384 * 2 + 8192 * 2) * 4>>>(
        w_fc1, b_fc1, w_fc2, b_fc2, g2, be2, out);
}

// round 4
// speedup vs baseline: 1.4105x; 1.4105x over previous
#include <cuda_runtime.h>
#include <cstdint>

#define Bsz 16
#define HW 16384          // H*W per batch
#define Cdim 128
#define QKVN 384
#define NHEADS 4
#define HDp 32
#define SHIFT 4
#define EPSLN 1e-3f
#define SCALEQ 0.17677669529663689f
#define M_TOTAL (Bsz * HW)   // 262144 rows

// ---- scratch (static device globals; no runtime allocation) ----
__device__ float g_qkv[(size_t)M_TOTAL * QKVN];   // ~402 MB
__device__ float g_att[(size_t)M_TOTAL * Cdim];   // ~134 MB

// row m (window-ordered) -> source/dest token index in (B, H*W) layout
__device__ __forceinline__ int win_row_to_token(int m) {
    int b   = m >> 14;
    int r   = m & 16383;
    int win = r >> 6;
    int n   = r & 63;
    int hb  = win >> 4;
    int wb  = win & 15;
    int h   = ((hb << 3) + (n >> 3) + SHIFT) & 127;
    int w   = ((wb << 3) + (n & 7) + SHIFT) & 127;
    return (b << 14) + (h << 7) + w;
}

// ===================== warp-MMA (tf32) helpers =====================
__device__ __forceinline__ float to_tf32(float x) {
    float y;
    asm("cvt.rna.tf32.f32 %0, %1;" : "=f"(y) : "f"(x));
    return y;
}
__device__ __forceinline__ uint32_t fbits(float x) { return __float_as_uint(x); }

// D += A(16x8) * B(8x8), tf32 inputs, f32 accum
__device__ __forceinline__ void mma168(float* c, const uint32_t* a, const uint32_t* b) {
    asm volatile(
        "mma.sync.aligned.m16n8k8.row.col.f32.tf32.tf32.f32 "
        "{%0,%1,%2,%3}, {%4,%5,%6,%7}, {%8,%9}, {%0,%1,%2,%3};"
        : "+f"(c[0]), "+f"(c[1]), "+f"(c[2]), "+f"(c[3])
        : "r"(a[0]), "r"(a[1]), "r"(a[2]), "r"(a[3]), "r"(b[0]), "r"(b[1]));
}

// ============================================================
// Kernel A: QKV GEMM with shifted-window gather on A rows.
// ============================================================
__global__ __launch_bounds__(256) void qkv_kernel(
    const float* __restrict__ x, const float* __restrict__ w,
    const float* __restrict__ bias) {
    __shared__ float As[128][17];
    __shared__ float Bs[16][68];
    const int tid   = threadIdx.x;
    const int mbase = blockIdx.y << 7;
    const int nbase = blockIdx.x << 6;
    const int ty    = tid >> 4;
    const int tx    = tid & 15;

    const int lr = tid >> 1;
    const int k8 = (tid & 1) << 3;
    const float* arow = x + (size_t)win_row_to_token(mbase + lr) * Cdim;

    const int kb = tid >> 4;
    const int n4 = (tid & 15) << 2;

    float acc[8][4];
#pragma unroll
    for (int i = 0; i < 8; i++)
#pragma unroll
        for (int j = 0; j < 4; j++) acc[i][j] = 0.f;

    for (int kc = 0; kc < 128; kc += 16) {
        float4 a0 = *(const float4*)(arow + kc + k8);
        float4 a1 = *(const float4*)(arow + kc + k8 + 4);
        As[lr][k8 + 0] = a0.x; As[lr][k8 + 1] = a0.y;
        As[lr][k8 + 2] = a0.z; As[lr][k8 + 3] = a0.w;
        As[lr][k8 + 4] = a1.x; As[lr][k8 + 5] = a1.y;
        As[lr][k8 + 6] = a1.z; As[lr][k8 + 7] = a1.w;
        *(float4*)&Bs[kb][n4] =
            *(const float4*)(w + (size_t)(kc + kb) * QKVN + nbase + n4);
        __syncthreads();
#pragma unroll
        for (int k = 0; k < 16; k++) {
            float4 bb = *(float4*)&Bs[k][tx << 2];
#pragma unroll
            for (int i = 0; i < 8; i++) {
                float a = As[(ty << 3) + i][k];
                acc[i][0] = fmaf(a, bb.x, acc[i][0]);
                acc[i][1] = fmaf(a, bb.y, acc[i][1]);
                acc[i][2] = fmaf(a, bb.z, acc[i][2]);
                acc[i][3] = fmaf(a, bb.w, acc[i][3]);
            }
        }
        __syncthreads();
    }
    float4 bv = *(const float4*)(bias + nbase + (tx << 2));
#pragma unroll
    for (int i = 0; i < 8; i++) {
        float4 o = make_float4(acc[i][0] + bv.x, acc[i][1] + bv.y,
                               acc[i][2] + bv.z, acc[i][3] + bv.w);
        *(float4*)&g_qkv[(size_t)(mbase + (ty << 3) + i) * QKVN + nbase + (tx << 2)] = o;
    }
}

// ============================================================
// Kernel B: windowed attention. One block per (window, head), 128 threads.
// ============================================================
__global__ __launch_bounds__(128) void attn_kernel(
    const float* __restrict__ bias_table, const int* __restrict__ rel_index,
    const float* __restrict__ mask) {
    __shared__ float qs[64][33], ks[64][33], vs[64][33];
    __shared__ float at[64][65];
    const int win  = blockIdx.x;
    const int head = blockIdx.y;
    const int wimg = win & 255;
    const int tid  = threadIdx.x;

    const float* base = g_qkv + (size_t)win * 64 * QKVN + head * HDp;
    for (int idx = tid; idx < 64 * 32; idx += 128) {
        int n = idx >> 5, d = idx & 31;
        const float* p = base + (size_t)n * QKVN + d;
        qs[n][d] = p[0] * SCALEQ;
        ks[n][d] = p[128];
        vs[n][d] = p[256];
    }
    __syncthreads();

    for (int idx = tid; idx < 4096; idx += 128) {
        int n = idx >> 6, mcol = idx & 63;
        float s = 0.f;
#pragma unroll
        for (int d = 0; d < 32; d++) s = fmaf(qs[n][d], ks[mcol][d], s);
        s += bias_table[rel_index[idx] * NHEADS + head];
        s += mask[(size_t)wimg * 4096 + idx];
        at[n][mcol] = s;
    }
    __syncthreads();

    {
        int row = tid >> 1, half = tid & 1;
        int m0 = half << 5;
        float mx = -1e30f;
        for (int m = m0; m < m0 + 32; m++) mx = fmaxf(mx, at[row][m]);
        mx = fmaxf(mx, __shfl_xor_sync(0xffffffffu, mx, 1));
        float s = 0.f;
        for (int m = m0; m < m0 + 32; m++) {
            float e = __expf(at[row][m] - mx);
            at[row][m] = e;
            s += e;
        }
        s += __shfl_xor_sync(0xffffffffu, s, 1);
        float inv = 1.0f / s;
        for (int m = m0; m < m0 + 32; m++) at[row][m] *= inv;
    }
    __syncthreads();

    for (int idx = tid; idx < 2048; idx += 128) {
        int n = idx >> 5, d = idx & 31;
        float s = 0.f;
#pragma unroll
        for (int m = 0; m < 64; m++) s = fmaf(at[n][m], vs[m][d], s);
        g_att[((size_t)win * 64 + n) * Cdim + head * HDp + d] = s;
    }
}

// ============================================================
// Kernel C: proj GEMM + window-reverse/unshift + LayerNorm + residual.
// ============================================================
__global__ __launch_bounds__(256) void proj_kernel(
    const float* __restrict__ x, const float* __restrict__ wp_g,
    const float* __restrict__ bp, const float* __restrict__ g1,
    const float* __restrict__ be1, float* __restrict__ out) {
    extern __shared__ float sm[];
    float* wp = sm;
    float* As = sm + 16384;
    const int tid = threadIdx.x;
    const int mbase = blockIdx.x << 6;

    for (int i = tid; i < 4096; i += 256) {
        int k = i >> 5, n4 = (i & 31) << 2;
        *(float4*)&wp[k * 128 + n4] = *(const float4*)(wp_g + k * 128 + n4);
    }
    for (int i = tid; i < 2048; i += 256) {
        int r = i >> 5, n4 = (i & 31) << 2;
        *(float4*)&As[r * 128 + n4] =
            *(const float4*)(g_att + ((size_t)(mbase + r)) * Cdim + n4);
    }
    __syncthreads();

    const int ty = tid >> 5, tx = tid & 31;
    float acc[8][4];
#pragma unroll
    for (int i = 0; i < 8; i++)
#pragma unroll
        for (int j = 0; j < 4; j++) acc[i][j] = 0.f;

#pragma unroll 4
    for (int k = 0; k < 128; k++) {
        float4 bb = *(float4*)&wp[k * 128 + (tx << 2)];
#pragma unroll
        for (int i = 0; i < 8; i++) {
            float a = As[((ty << 3) + i) * 128 + k];
            acc[i][0] = fmaf(a, bb.x, acc[i][0]);
            acc[i][1] = fmaf(a, bb.y, acc[i][1]);
            acc[i][2] = fmaf(a, bb.z, acc[i][2]);
            acc[i][3] = fmaf(a, bb.w, acc[i][3]);
        }
    }

    float4 bp4  = *(const float4*)(bp  + (tx << 2));
    float4 g14  = *(const float4*)(g1  + (tx << 2));
    float4 be14 = *(const float4*)(be1 + (tx << 2));
#pragma unroll
    for (int i = 0; i < 8; i++) {
        float v0 = acc[i][0] + bp4.x, v1 = acc[i][1] + bp4.y;
        float v2 = acc[i][2] + bp4.z, v3 = acc[i][3] + bp4.w;
        float s = v0 + v1 + v2 + v3;
#pragma unroll
        for (int o = 16; o > 0; o >>= 1) s += __shfl_xor_sync(0xffffffffu, s, o);
        float mean = s * (1.0f / 128.0f);
        float d0 = v0 - mean, d1 = v1 - mean, d2 = v2 - mean, d3 = v3 - mean;
        float q = d0 * d0 + d1 * d1 + d2 * d2 + d3 * d3;
#pragma unroll
        for (int o = 16; o > 0; o >>= 1) q += __shfl_xor_sync(0xffffffffu, q, o);
        float rs = rsqrtf(q * (1.0f / 128.0f) + EPSLN);

        int tok = win_row_to_token(mbase + (ty << 3) + i);
        size_t off = (size_t)tok * Cdim + (tx << 2);
        float4 xr = *(const float4*)(x + off);
        float4 o4;
        o4.x = xr.x + d0 * rs * g14.x + be14.x;
        o4.y = xr.y + d1 * rs * g14.y + be14.y;
        o4.z = xr.z + d2 * rs * g14.z + be14.z;
        o4.w = xr.w + d3 * rs * g14.w + be14.w;
        *(float4*)(out + off) = o4;
    }
}

// ============================================================
// Kernel D: tf32 warp-MMA MLP. M=128 rows/CTA, 256 threads (8 warps).
// HID in 8 slabs of 64:
//   fc1: H1[128x64] = A[128x128] @ W1_slab   (mma.sync tf32)
//   bias + exact-erf GELU in regs -> Hs (tf32)
//   fc2: acc[128x128] += Hs[128x64] @ W2_slab (mma.sync tf32, regs persist)
// Epilogue: +b2, LayerNorm, residual, in-place on io.
// Warp tiling: rows (w>>1)*32, fc1 cols (w&1)*32, fc2 cols (w&1)*64.
// smem pitches chosen conflict-free: A/ob 132, W1 72, Hs 68, W2 136.
// ============================================================
#define PA  132
#define PB1 72
#define PH  68
#define PW2 136
#define MLP_SMEM_FLOATS (128 * PA + 128 * PB1 + 128 * PH + 64 * PW2)
#define MLP_SMEM_BYTES  (MLP_SMEM_FLOATS * 4)

__global__ __launch_bounds__(256, 1) void mlp_mma_kernel(
    const float* __restrict__ w1g, const float* __restrict__ b1,
    const float* __restrict__ w2g, const float* __restrict__ b2,
    const float* __restrict__ g2v, const float* __restrict__ be2v,
    float* __restrict__ io) {
    extern __shared__ float sm[];
    float* As  = sm;                       // 128 x PA (tf32)
    float* Bs  = As + 128 * PA;            // 128 x PB1 (W1 slab, k x n)
    float* Hs  = Bs + 128 * PB1;           // 128 x PH  (gelu out, tf32)
    float* W2s = Hs + 128 * PH;            // 64 x PW2  (W2 slab, k x n)

    const int tid  = threadIdx.x;
    const int w    = tid >> 5;
    const int lane = tid & 31;
    const int mbase = blockIdx.x << 7;

    const int base_m  = (w >> 1) << 5;     // 0,32,64,96
    const int base_n1 = (w & 1) << 5;      // fc1: 0 or 32
    const int base_n2 = (w & 1) << 6;      // fc2: 0 or 64

    // ---- load A = x1 tile [128 x 128], tf32-converted ----
    for (int i = tid; i < 4096; i += 256) {
        int r = i >> 5, c4 = (i & 31) << 2;
        float4 v = *(const float4*)(io + (((size_t)(mbase + r)) << 7) + c4);
        float* p = As + r * PA + c4;
        p[0] = to_tf32(v.x); p[1] = to_tf32(v.y);
        p[2] = to_tf32(v.z); p[3] = to_tf32(v.w);
    }

    float c2[2][8][4];
#pragma unroll
    for (int mt = 0; mt < 2; mt++)
#pragma unroll
        for (int nt = 0; nt < 8; nt++)
#pragma unroll
            for (int j = 0; j < 4; j++) c2[mt][nt][j] = 0.f;

    for (int c = 0; c < 8; ++c) {
        __syncthreads();   // A ready (c=0); prev fc2 done before weight overwrite
        // W1 slab: Bs[k][n] = w1[k][64c + n], k=0..127, n=0..63
        for (int i = tid; i < 2048; i += 256) {
            int k = i >> 4, n4 = (i & 15) << 2;
            float4 v = *(const float4*)(w1g + (size_t)k * 512 + (c << 6) + n4);
            float* p = Bs + k * PB1 + n4;
            p[0] = to_tf32(v.x); p[1] = to_tf32(v.y);
            p[2] = to_tf32(v.z); p[3] = to_tf32(v.w);
        }
        // W2 slab: W2s[k][n] = w2[64c + k][n], k=0..63, n=0..127
        for (int i = tid; i < 2048; i += 256) {
            int k = i >> 5, n4 = (i & 31) << 2;
            float4 v = *(const float4*)(w2g + (((size_t)((c << 6) + k)) << 7) + n4);
            float* p = W2s + k * PW2 + n4;
            p[0] = to_tf32(v.x); p[1] = to_tf32(v.y);
            p[2] = to_tf32(v.z); p[3] = to_tf32(v.w);
        }
        __syncthreads();

        // ---- fc1: c1[2][4] tiles (32 rows x 32 cols per warp) ----
        float c1[2][4][4];
#pragma unroll
        for (int mt = 0; mt < 2; mt++)
#pragma unroll
            for (int nt = 0; nt < 4; nt++)
#pragma unroll
                for (int j = 0; j < 4; j++) c1[mt][nt][j] = 0.f;

        const int ar = lane >> 2, ac = lane & 3;
        const int bn = base_n1 + (lane >> 2);
#pragma unroll
        for (int k0 = 0; k0 < 128; k0 += 8) {
            uint32_t a[2][4];
#pragma unroll
            for (int mt = 0; mt < 2; mt++) {
                const float* p = As + (base_m + (mt << 4) + ar) * PA + k0 + ac;
                a[mt][0] = fbits(p[0]);
                a[mt][1] = fbits(p[8 * PA]);
                a[mt][2] = fbits(p[4]);
                a[mt][3] = fbits(p[8 * PA + 4]);
            }
            uint32_t b[4][2];
#pragma unroll
            for (int nt = 0; nt < 4; nt++) {
                const float* p = Bs + (k0 + ac) * PB1 + bn + (nt << 3);
                b[nt][0] = fbits(p[0]);
                b[nt][1] = fbits(p[4 * PB1]);
            }
#pragma unroll
            for (int mt = 0; mt < 2; mt++)
#pragma unroll
                for (int nt = 0; nt < 4; nt++)
                    mma168(c1[mt][nt], a[mt], b[nt]);
        }

        // ---- bias + GELU -> Hs (tf32) ----
#pragma unroll
        for (int mt = 0; mt < 2; mt++) {
            int r0 = base_m + (mt << 4) + (lane >> 2);
#pragma unroll
            for (int nt = 0; nt < 4; nt++) {
                int col = base_n1 + (nt << 3) + ((lane & 3) << 1);
                float bb0 = __ldg(&b1[(c << 6) + col]);
                float bb1 = __ldg(&b1[(c << 6) + col + 1]);
#pragma unroll
                for (int half = 0; half < 2; half++) {
                    int r = r0 + half * 8;
                    float v0 = c1[mt][nt][half * 2 + 0] + bb0;
                    float v1 = c1[mt][nt][half * 2 + 1] + bb1;
                    v0 = 0.5f * v0 * (1.0f + erff(v0 * 0.70710678118654752f));
                    v1 = 0.5f * v1 * (1.0f + erff(v1 * 0.70710678118654752f));
                    Hs[r * PH + col]     = to_tf32(v0);
                    Hs[r * PH + col + 1] = to_tf32(v1);
                }
            }
        }
        __syncthreads();

        // ---- fc2: acc += Hs[128x64] @ W2s[64x128] ----
#pragma unroll
        for (int k0 = 0; k0 < 64; k0 += 8) {
            uint32_t a[2][4];
#pragma unroll
            for (int mt = 0; mt < 2; mt++) {
                const float* p = Hs + (base_m + (mt << 4) + ar) * PH + k0 + ac;
                a[mt][0] = fbits(p[0]);
                a[mt][1] = fbits(p[8 * PH]);
                a[mt][2] = fbits(p[4]);
                a[mt][3] = fbits(p[8 * PH + 4]);
            }
            uint32_t b[8][2];
            const int bn2 = base_n2 + (lane >> 2);
#pragma unroll
            for (int nt = 0; nt < 8; nt++) {
                const float* p = W2s + (k0 + ac) * PW2 + bn2 + (nt << 3);
                b[nt][0] = fbits(p[0]);
                b[nt][1] = fbits(p[4 * PW2]);
            }
#pragma unroll
            for (int mt = 0; mt < 2; mt++)
#pragma unroll
                for (int nt = 0; nt < 8; nt++)
                    mma168(c2[mt][nt], a[mt], b[nt]);
        }
    }

    // ---- epilogue: +b2 -> smem, LN, residual (in place) ----
    __syncthreads();
    float* ob = Bs;   // reuse: 128 x PA fits in Bs+Hs+W2s region (ob uses PA pitch)
#pragma unroll
    for (int mt = 0; mt < 2; mt++) {
        int r0 = base_m + (mt << 4) + (lane >> 2);
#pragma unroll
        for (int nt = 0; nt < 8; nt++) {
            int col = base_n2 + (nt << 3) + ((lane & 3) << 1);
            float bb0 = __ldg(&b2[col]);
            float bb1 = __ldg(&b2[col + 1]);
#pragma unroll
            for (int half = 0; half < 2; half++) {
                int r = r0 + half * 8;
                ob[r * PA + col]     = c2[mt][nt][half * 2 + 0] + bb0;
                ob[r * PA + col + 1] = c2[mt][nt][half * 2 + 1] + bb1;
            }
        }
    }
    __syncthreads();

    {
        int r   = tid >> 1;
        int h64 = (tid & 1) << 6;
        float s1 = 0.f, s2 = 0.f;
#pragma unroll
        for (int j = 0; j < 64; j += 4) {
            float4 v = *(float4*)&ob[r * PA + h64 + j];
            s1 += v.x + v.y + v.z + v.w;
            s2 += v.x * v.x + v.y * v.y + v.z * v.z + v.w * v.w;
        }
        s1 += __shfl_xor_sync(0xffffffffu, s1, 1);
        s2 += __shfl_xor_sync(0xffffffffu, s2, 1);
        float mean = s1 * (1.0f / 128.0f);
        float var  = s2 * (1.0f / 128.0f) - mean * mean;
        float rs   = rsqrtf(var + EPSLN);
        size_t rowoff = ((size_t)(mbase + r)) << 7;
#pragma unroll
        for (int j = 0; j < 64; j += 4) {
            int cc = h64 + j;
            float4 v  = *(float4*)&ob[r * PA + cc];
            float4 xr = *(const float4*)(io + rowoff + cc);
            float4 gg = *(const float4*)(g2v + cc);
            float4 bb = *(const float4*)(be2v + cc);
            float4 o;
            o.x = xr.x + (v.x - mean) * rs * gg.x + bb.x;
            o.y = xr.y + (v.y - mean) * rs * gg.y + bb.y;
            o.z = xr.z + (v.z - mean) * rs * gg.z + bb.z;
            o.w = xr.w + (v.w - mean) * rs * gg.w + bb.w;
            *(float4*)(io + rowoff + cc) = o;
        }
    }
}

// ============================================================
extern "C" void kernel_launch(void* const* d_in, const int* in_sizes, int n_in,
                              void* d_out, int out_size) {
    const float* x          = (const float*)d_in[0];
    const float* w_qkv      = (const float*)d_in[1];
    const float* b_qkv      = (const float*)d_in[2];
    const float* bias_table = (const float*)d_in[3];
    const float* w_proj     = (const float*)d_in[4];
    const float* b_proj     = (const float*)d_in[5];
    const float* g1         = (const float*)d_in[6];
    const float* be1        = (const float*)d_in[7];
    const float* w_fc1      = (const float*)d_in[8];
    const float* b_fc1      = (const float*)d_in[9];
    const float* w_fc2      = (const float*)d_in[10];
    const float* b_fc2      = (const float*)d_in[11];
    const float* g2         = (const float*)d_in[12];
    const float* be2        = (const float*)d_in[13];
    const int*   rel_index  = (const int*)d_in[14];
    const float* attn_mask  = (const float*)d_in[15];
    float* out = (float*)d_out;

    cudaFuncSetAttribute(proj_kernel, cudaFuncAttributeMaxDynamicSharedMemorySize,
                         (16384 + 8192) * 4);
    cudaFuncSetAttribute(mlp_mma_kernel, cudaFuncAttributeMaxDynamicSharedMemorySize,
                         MLP_SMEM_BYTES);

    qkv_kernel<<<dim3(6, M_TOTAL / 128), 256>>>(x, w_qkv, b_qkv);
    attn_kernel<<<dim3(4096, 4), 128>>>(bias_table, rel_index, attn_mask);
    proj_kernel<<<M_TOTAL / 64, 256, (16384 + 8192) * 4>>>(x, w_proj, b_proj, g1, be1, out);
    mlp_mma_kernel<<<M_TOTAL / 128, 256, MLP_SMEM_BYTES>>>(
        w_fc1, b_fc1, w_fc2, b_fc2, g2, be2, out);
}

// round 5
// speedup vs baseline: 1.4276x; 1.0122x over previous
#include <cuda_runtime.h>
#include <cstdint>

#define Bsz 16
#define HW 16384          // H*W per batch
#define Cdim 128
#define QKVN 384
#define NHEADS 4
#define HDp 32
#define SHIFT 4
#define EPSLN 1e-3f
#define SCALEQ 0.17677669529663689f
#define M_TOTAL (Bsz * HW)   // 262144 rows

// ---- scratch (static device globals; no runtime allocation) ----
__device__ float g_qkv[(size_t)M_TOTAL * QKVN];   // ~402 MB
__device__ float g_att[(size_t)M_TOTAL * Cdim];   // ~134 MB

// row m (window-ordered) -> source/dest token index in (B, H*W) layout
__device__ __forceinline__ int win_row_to_token(int m) {
    int b   = m >> 14;
    int r   = m & 16383;
    int win = r >> 6;
    int n   = r & 63;
    int hb  = win >> 4;
    int wb  = win & 15;
    int h   = ((hb << 3) + (n >> 3) + SHIFT) & 127;
    int w   = ((wb << 3) + (n & 7) + SHIFT) & 127;
    return (b << 14) + (h << 7) + w;
}

// ===================== warp-MMA (tf32) helpers =====================
__device__ __forceinline__ float to_tf32(float x) {
    float y;
    asm("cvt.rna.tf32.f32 %0, %1;" : "=f"(y) : "f"(x));
    return y;
}
__device__ __forceinline__ uint32_t fbits(float x) { return __float_as_uint(x); }

// D += A(16x8) * B(8x8), tf32 inputs, f32 accum
__device__ __forceinline__ void mma168(float* c, const uint32_t* a, const uint32_t* b) {
    asm volatile(
        "mma.sync.aligned.m16n8k8.row.col.f32.tf32.tf32.f32 "
        "{%0,%1,%2,%3}, {%4,%5,%6,%7}, {%8,%9}, {%0,%1,%2,%3};"
        : "+f"(c[0]), "+f"(c[1]), "+f"(c[2]), "+f"(c[3])
        : "r"(a[0]), "r"(a[1]), "r"(a[2]), "r"(a[3]), "r"(b[0]), "r"(b[1]));
}

// shared pitches (conflict-free, proven in R4 mlp kernel)
#define PAQ 132
#define PBQ 136
#define GEMM_SMEM_BYTES ((128 * PAQ + 128 * PBQ) * 4)

// ============================================================
// Kernel A: QKV GEMM, warp-MMA tf32, gathered A rows.
// grid (3, M/128): N-tile 128 of 384, M-tile 128. 256 thr, 8 warps.
// Warp tile 32(M) x 64(N): c[2][8][4].
// ============================================================
__global__ __launch_bounds__(256, 1) void qkv_mma_kernel(
    const float* __restrict__ x, const float* __restrict__ wq,
    const float* __restrict__ bias) {
    extern __shared__ float sm[];
    float* As = sm;               // 128 x PAQ
    float* Bs = As + 128 * PAQ;   // 128 x PBQ

    const int tid  = threadIdx.x;
    const int w    = tid >> 5;
    const int lane = tid & 31;
    const int mbase = blockIdx.y << 7;
    const int nbase = blockIdx.x << 7;

    const int base_m = (w >> 1) << 5;
    const int base_n = (w & 1) << 6;

    for (int i = tid; i < 4096; i += 256) {
        int r = i >> 5, c4 = (i & 31) << 2;
        float4 v = *(const float4*)(x + (size_t)win_row_to_token(mbase + r) * Cdim + c4);
        float* p = As + r * PAQ + c4;
        p[0] = to_tf32(v.x); p[1] = to_tf32(v.y);
        p[2] = to_tf32(v.z); p[3] = to_tf32(v.w);
    }
    for (int i = tid; i < 4096; i += 256) {
        int k = i >> 5, n4 = (i & 31) << 2;
        float4 v = *(const float4*)(wq + (size_t)k * QKVN + nbase + n4);
        float* p = Bs + k * PBQ + n4;
        p[0] = to_tf32(v.x); p[1] = to_tf32(v.y);
        p[2] = to_tf32(v.z); p[3] = to_tf32(v.w);
    }
    __syncthreads();

    float c2[2][8][4];
#pragma unroll
    for (int mt = 0; mt < 2; mt++)
#pragma unroll
        for (int nt = 0; nt < 8; nt++)
#pragma unroll
            for (int j = 0; j < 4; j++) c2[mt][nt][j] = 0.f;

    const int ar = lane >> 2, ac = lane & 3;
    const int bn = base_n + (lane >> 2);
#pragma unroll
    for (int k0 = 0; k0 < 128; k0 += 8) {
        uint32_t a[2][4];
#pragma unroll
        for (int mt = 0; mt < 2; mt++) {
            const float* p = As + (base_m + (mt << 4) + ar) * PAQ + k0 + ac;
            a[mt][0] = fbits(p[0]);
            a[mt][1] = fbits(p[8 * PAQ]);
            a[mt][2] = fbits(p[4]);
            a[mt][3] = fbits(p[8 * PAQ + 4]);
        }
        uint32_t b[8][2];
#pragma unroll
        for (int nt = 0; nt < 8; nt++) {
            const float* p = Bs + (k0 + ac) * PBQ + bn + (nt << 3);
            b[nt][0] = fbits(p[0]);
            b[nt][1] = fbits(p[4 * PBQ]);
        }
#pragma unroll
        for (int mt = 0; mt < 2; mt++)
#pragma unroll
            for (int nt = 0; nt < 8; nt++)
                mma168(c2[mt][nt], a[mt], b[nt]);
    }

    // epilogue: +bias, store to g_qkv
#pragma unroll
    for (int mt = 0; mt < 2; mt++) {
        int r0 = base_m + (mt << 4) + (lane >> 2);
#pragma unroll
        for (int nt = 0; nt < 8; nt++) {
            int col = base_n + (nt << 3) + ((lane & 3) << 1);
            float bb0 = __ldg(&bias[nbase + col]);
            float bb1 = __ldg(&bias[nbase + col + 1]);
#pragma unroll
            for (int half = 0; half < 2; half++) {
                int r = r0 + half * 8;
                float2 o = make_float2(c2[mt][nt][half * 2 + 0] + bb0,
                                       c2[mt][nt][half * 2 + 1] + bb1);
                *(float2*)&g_qkv[(size_t)(mbase + r) * QKVN + nbase + col] = o;
            }
        }
    }
}

// ============================================================
// Kernel B: windowed attention. One block per (window, head), 128 threads.
// ============================================================
__global__ __launch_bounds__(128) void attn_kernel(
    const float* __restrict__ bias_table, const int* __restrict__ rel_index,
    const float* __restrict__ mask) {
    __shared__ float qs[64][33], ks[64][33], vs[64][33];
    __shared__ float at[64][65];
    const int win  = blockIdx.x;
    const int head = blockIdx.y;
    const int wimg = win & 255;
    const int tid  = threadIdx.x;

    const float* base = g_qkv + (size_t)win * 64 * QKVN + head * HDp;
    for (int idx = tid; idx < 64 * 32; idx += 128) {
        int n = idx >> 5, d = idx & 31;
        const float* p = base + (size_t)n * QKVN + d;
        qs[n][d] = p[0] * SCALEQ;
        ks[n][d] = p[128];
        vs[n][d] = p[256];
    }
    __syncthreads();

    for (int idx = tid; idx < 4096; idx += 128) {
        int n = idx >> 6, mcol = idx & 63;
        float s = 0.f;
#pragma unroll
        for (int d = 0; d < 32; d++) s = fmaf(qs[n][d], ks[mcol][d], s);
        s += bias_table[rel_index[idx] * NHEADS + head];
        s += mask[(size_t)wimg * 4096 + idx];
        at[n][mcol] = s;
    }
    __syncthreads();

    {
        int row = tid >> 1, half = tid & 1;
        int m0 = half << 5;
        float mx = -1e30f;
        for (int m = m0; m < m0 + 32; m++) mx = fmaxf(mx, at[row][m]);
        mx = fmaxf(mx, __shfl_xor_sync(0xffffffffu, mx, 1));
        float s = 0.f;
        for (int m = m0; m < m0 + 32; m++) {
            float e = __expf(at[row][m] - mx);
            at[row][m] = e;
            s += e;
        }
        s += __shfl_xor_sync(0xffffffffu, s, 1);
        float inv = 1.0f / s;
        for (int m = m0; m < m0 + 32; m++) at[row][m] *= inv;
    }
    __syncthreads();

    for (int idx = tid; idx < 2048; idx += 128) {
        int n = idx >> 5, d = idx & 31;
        float s = 0.f;
#pragma unroll
        for (int m = 0; m < 64; m++) s = fmaf(at[n][m], vs[m][d], s);
        g_att[((size_t)win * 64 + n) * Cdim + head * HDp + d] = s;
    }
}

// ============================================================
// Kernel C: proj GEMM (warp-MMA tf32) + window-reverse/unshift + LN + residual.
// grid M/128, 256 threads, warp tile 32x64.
// ============================================================
__global__ __launch_bounds__(256, 1) void proj_mma_kernel(
    const float* __restrict__ x, const float* __restrict__ wp_g,
    const float* __restrict__ bp, const float* __restrict__ g1,
    const float* __restrict__ be1, float* __restrict__ out) {
    extern __shared__ float sm[];
    float* As = sm;               // 128 x PAQ
    float* Bs = As + 128 * PAQ;   // 128 x PBQ (later reused as ob, pitch PAQ)

    const int tid  = threadIdx.x;
    const int w    = tid >> 5;
    const int lane = tid & 31;
    const int mbase = blockIdx.x << 7;

    const int base_m = (w >> 1) << 5;
    const int base_n = (w & 1) << 6;

    for (int i = tid; i < 4096; i += 256) {
        int r = i >> 5, c4 = (i & 31) << 2;
        float4 v = *(const float4*)(g_att + (((size_t)(mbase + r)) << 7) + c4);
        float* p = As + r * PAQ + c4;
        p[0] = to_tf32(v.x); p[1] = to_tf32(v.y);
        p[2] = to_tf32(v.z); p[3] = to_tf32(v.w);
    }
    for (int i = tid; i < 4096; i += 256) {
        int k = i >> 5, n4 = (i & 31) << 2;
        float4 v = *(const float4*)(wp_g + (size_t)k * Cdim + n4);
        float* p = Bs + k * PBQ + n4;
        p[0] = to_tf32(v.x); p[1] = to_tf32(v.y);
        p[2] = to_tf32(v.z); p[3] = to_tf32(v.w);
    }
    __syncthreads();

    float c2[2][8][4];
#pragma unroll
    for (int mt = 0; mt < 2; mt++)
#pragma unroll
        for (int nt = 0; nt < 8; nt++)
#pragma unroll
            for (int j = 0; j < 4; j++) c2[mt][nt][j] = 0.f;

    const int ar = lane >> 2, ac = lane & 3;
    const int bn = base_n + (lane >> 2);
#pragma unroll
    for (int k0 = 0; k0 < 128; k0 += 8) {
        uint32_t a[2][4];
#pragma unroll
        for (int mt = 0; mt < 2; mt++) {
            const float* p = As + (base_m + (mt << 4) + ar) * PAQ + k0 + ac;
            a[mt][0] = fbits(p[0]);
            a[mt][1] = fbits(p[8 * PAQ]);
            a[mt][2] = fbits(p[4]);
            a[mt][3] = fbits(p[8 * PAQ + 4]);
        }
        uint32_t b[8][2];
#pragma unroll
        for (int nt = 0; nt < 8; nt++) {
            const float* p = Bs + (k0 + ac) * PBQ + bn + (nt << 3);
            b[nt][0] = fbits(p[0]);
            b[nt][1] = fbits(p[4 * PBQ]);
        }
#pragma unroll
        for (int mt = 0; mt < 2; mt++)
#pragma unroll
            for (int nt = 0; nt < 8; nt++)
                mma168(c2[mt][nt], a[mt], b[nt]);
    }

    // stage biased output in smem (reuse Bs region; pitch PAQ)
    __syncthreads();
    float* ob = Bs;
#pragma unroll
    for (int mt = 0; mt < 2; mt++) {
        int r0 = base_m + (mt << 4) + (lane >> 2);
#pragma unroll
        for (int nt = 0; nt < 8; nt++) {
            int col = base_n + (nt << 3) + ((lane & 3) << 1);
            float bb0 = __ldg(&bp[col]);
            float bb1 = __ldg(&bp[col + 1]);
#pragma unroll
            for (int half = 0; half < 2; half++) {
                int r = r0 + half * 8;
                ob[r * PAQ + col]     = c2[mt][nt][half * 2 + 0] + bb0;
                ob[r * PAQ + col + 1] = c2[mt][nt][half * 2 + 1] + bb1;
            }
        }
    }
    __syncthreads();

    {   // LayerNorm + residual with unshift scatter
        int r   = tid >> 1;
        int h64 = (tid & 1) << 6;
        float s1 = 0.f, s2 = 0.f;
#pragma unroll
        for (int j = 0; j < 64; j += 4) {
            float4 v = *(float4*)&ob[r * PAQ + h64 + j];
            s1 += v.x + v.y + v.z + v.w;
            s2 += v.x * v.x + v.y * v.y + v.z * v.z + v.w * v.w;
        }
        s1 += __shfl_xor_sync(0xffffffffu, s1, 1);
        s2 += __shfl_xor_sync(0xffffffffu, s2, 1);
        float mean = s1 * (1.0f / 128.0f);
        float var  = s2 * (1.0f / 128.0f) - mean * mean;
        float rs   = rsqrtf(var + EPSLN);
        size_t rowoff = ((size_t)win_row_to_token(mbase + r)) << 7;
#pragma unroll
        for (int j = 0; j < 64; j += 4) {
            int cc = h64 + j;
            float4 v  = *(float4*)&ob[r * PAQ + cc];
            float4 xr = *(const float4*)(x + rowoff + cc);
            float4 gg = *(const float4*)(g1 + cc);
            float4 bb = *(const float4*)(be1 + cc);
            float4 o;
            o.x = xr.x + (v.x - mean) * rs * gg.x + bb.x;
            o.y = xr.y + (v.y - mean) * rs * gg.y + bb.y;
            o.z = xr.z + (v.z - mean) * rs * gg.z + bb.z;
            o.w = xr.w + (v.w - mean) * rs * gg.w + bb.w;
            *(float4*)(out + rowoff + cc) = o;
        }
    }
}

// ============================================================
// Kernel D: tf32 warp-MMA MLP (unchanged from R4).
// ============================================================
#define PA  132
#define PB1 72
#define PH  68
#define PW2 136
#define MLP_SMEM_FLOATS (128 * PA + 128 * PB1 + 128 * PH + 64 * PW2)
#define MLP_SMEM_BYTES  (MLP_SMEM_FLOATS * 4)

__global__ __launch_bounds__(256, 1) void mlp_mma_kernel(
    const float* __restrict__ w1g, const float* __restrict__ b1,
    const float* __restrict__ w2g, const float* __restrict__ b2,
    const float* __restrict__ g2v, const float* __restrict__ be2v,
    float* __restrict__ io) {
    extern __shared__ float sm[];
    float* As  = sm;
    float* Bs  = As + 128 * PA;
    float* Hs  = Bs + 128 * PB1;
    float* W2s = Hs + 128 * PH;

    const int tid  = threadIdx.x;
    const int w    = tid >> 5;
    const int lane = tid & 31;
    const int mbase = blockIdx.x << 7;

    const int base_m  = (w >> 1) << 5;
    const int base_n1 = (w & 1) << 5;
    const int base_n2 = (w & 1) << 6;

    for (int i = tid; i < 4096; i += 256) {
        int r = i >> 5, c4 = (i & 31) << 2;
        float4 v = *(const float4*)(io + (((size_t)(mbase + r)) << 7) + c4);
        float* p = As + r * PA + c4;
        p[0] = to_tf32(v.x); p[1] = to_tf32(v.y);
        p[2] = to_tf32(v.z); p[3] = to_tf32(v.w);
    }

    float c2[2][8][4];
#pragma unroll
    for (int mt = 0; mt < 2; mt++)
#pragma unroll
        for (int nt = 0; nt < 8; nt++)
#pragma unroll
            for (int j = 0; j < 4; j++) c2[mt][nt][j] = 0.f;

    for (int c = 0; c < 8; ++c) {
        __syncthreads();
        for (int i = tid; i < 2048; i += 256) {
            int k = i >> 4, n4 = (i & 15) << 2;
            float4 v = *(const float4*)(w1g + (size_t)k * 512 + (c << 6) + n4);
            float* p = Bs + k * PB1 + n4;
            p[0] = to_tf32(v.x); p[1] = to_tf32(v.y);
            p[2] = to_tf32(v.z); p[3] = to_tf32(v.w);
        }
        for (int i = tid; i < 2048; i += 256) {
            int k = i >> 5, n4 = (i & 31) << 2;
            float4 v = *(const float4*)(w2g + (((size_t)((c << 6) + k)) << 7) + n4);
            float* p = W2s + k * PW2 + n4;
            p[0] = to_tf32(v.x); p[1] = to_tf32(v.y);
            p[2] = to_tf32(v.z); p[3] = to_tf32(v.w);
        }
        __syncthreads();

        float c1[2][4][4];
#pragma unroll
        for (int mt = 0; mt < 2; mt++)
#pragma unroll
            for (int nt = 0; nt < 4; nt++)
#pragma unroll
                for (int j = 0; j < 4; j++) c1[mt][nt][j] = 0.f;

        const int ar = lane >> 2, ac = lane & 3;
        const int bn = base_n1 + (lane >> 2);
#pragma unroll
        for (int k0 = 0; k0 < 128; k0 += 8) {
            uint32_t a[2][4];
#pragma unroll
            for (int mt = 0; mt < 2; mt++) {
                const float* p = As + (base_m + (mt << 4) + ar) * PA + k0 + ac;
                a[mt][0] = fbits(p[0]);
                a[mt][1] = fbits(p[8 * PA]);
                a[mt][2] = fbits(p[4]);
                a[mt][3] = fbits(p[8 * PA + 4]);
            }
            uint32_t b[4][2];
#pragma unroll
            for (int nt = 0; nt < 4; nt++) {
                const float* p = Bs + (k0 + ac) * PB1 + bn + (nt << 3);
                b[nt][0] = fbits(p[0]);
                b[nt][1] = fbits(p[4 * PB1]);
            }
#pragma unroll
            for (int mt = 0; mt < 2; mt++)
#pragma unroll
                for (int nt = 0; nt < 4; nt++)
                    mma168(c1[mt][nt], a[mt], b[nt]);
        }

#pragma unroll
        for (int mt = 0; mt < 2; mt++) {
            int r0 = base_m + (mt << 4) + (lane >> 2);
#pragma unroll
            for (int nt = 0; nt < 4; nt++) {
                int col = base_n1 + (nt << 3) + ((lane & 3) << 1);
                float bb0 = __ldg(&b1[(c << 6) + col]);
                float bb1 = __ldg(&b1[(c << 6) + col + 1]);
#pragma unroll
                for (int half = 0; half < 2; half++) {
                    int r = r0 + half * 8;
                    float v0 = c1[mt][nt][half * 2 + 0] + bb0;
                    float v1 = c1[mt][nt][half * 2 + 1] + bb1;
                    v0 = 0.5f * v0 * (1.0f + erff(v0 * 0.70710678118654752f));
                    v1 = 0.5f * v1 * (1.0f + erff(v1 * 0.70710678118654752f));
                    Hs[r * PH + col]     = to_tf32(v0);
                    Hs[r * PH + col + 1] = to_tf32(v1);
                }
            }
        }
        __syncthreads();

        const int bn2 = base_n2 + (lane >> 2);
#pragma unroll
        for (int k0 = 0; k0 < 64; k0 += 8) {
            uint32_t a[2][4];
#pragma unroll
            for (int mt = 0; mt < 2; mt++) {
                const float* p = Hs + (base_m + (mt << 4) + ar) * PH + k0 + ac;
                a[mt][0] = fbits(p[0]);
                a[mt][1] = fbits(p[8 * PH]);
                a[mt][2] = fbits(p[4]);
                a[mt][3] = fbits(p[8 * PH + 4]);
            }
            uint32_t b[8][2];
#pragma unroll
            for (int nt = 0; nt < 8; nt++) {
                const float* p = W2s + (k0 + ac) * PW2 + bn2 + (nt << 3);
                b[nt][0] = fbits(p[0]);
                b[nt][1] = fbits(p[4 * PW2]);
            }
#pragma unroll
            for (int mt = 0; mt < 2; mt++)
#pragma unroll
                for (int nt = 0; nt < 8; nt++)
                    mma168(c2[mt][nt], a[mt], b[nt]);
        }
    }

    __syncthreads();
    float* ob = Bs;
#pragma unroll
    for (int mt = 0; mt < 2; mt++) {
        int r0 = base_m + (mt << 4) + (lane >> 2);
#pragma unroll
        for (int nt = 0; nt < 8; nt++) {
            int col = base_n2 + (nt << 3) + ((lane & 3) << 1);
            float bb0 = __ldg(&b2[col]);
            float bb1 = __ldg(&b2[col + 1]);
#pragma unroll
            for (int half = 0; half < 2; half++) {
                int r = r0 + half * 8;
                ob[r * PA + col]     = c2[mt][nt][half * 2 + 0] + bb0;
                ob[r * PA + col + 1] = c2[mt][nt][half * 2 + 1] + bb1;
            }
        }
    }
    __syncthreads();

    {
        int r   = tid >> 1;
        int h64 = (tid & 1) << 6;
        float s1 = 0.f, s2 = 0.f;
#pragma unroll
        for (int j = 0; j < 64; j += 4) {
            float4 v = *(float4*)&ob[r * PA + h64 + j];
            s1 += v.x + v.y + v.z + v.w;
            s2 += v.x * v.x + v.y * v.y + v.z * v.z + v.w * v.w;
        }
        s1 += __shfl_xor_sync(0xffffffffu, s1, 1);
        s2 += __shfl_xor_sync(0xffffffffu, s2, 1);
        float mean = s1 * (1.0f / 128.0f);
        float var  = s2 * (1.0f / 128.0f) - mean * mean;
        float rs   = rsqrtf(var + EPSLN);
        size_t rowoff = ((size_t)(mbase + r)) << 7;
#pragma unroll
        for (int j = 0; j < 64; j += 4) {
            int cc = h64 + j;
            float4 v  = *(float4*)&ob[r * PA + cc];
            float4 xr = *(const float4*)(io + rowoff + cc);
            float4 gg = *(const float4*)(g2v + cc);
            float4 bb = *(const float4*)(be2v + cc);
            float4 o;
            o.x = xr.x + (v.x - mean) * rs * gg.x + bb.x;
            o.y = xr.y + (v.y - mean) * rs * gg.y + bb.y;
            o.z = xr.z + (v.z - mean) * rs * gg.z + bb.z;
            o.w = xr.w + (v.w - mean) * rs * gg.w + bb.w;
            *(float4*)(io + rowoff + cc) = o;
        }
    }
}

// ============================================================
extern "C" void kernel_launch(void* const* d_in, const int* in_sizes, int n_in,
                              void* d_out, int out_size) {
    const float* x          = (const float*)d_in[0];
    const float* w_qkv      = (const float*)d_in[1];
    const float* b_qkv      = (const float*)d_in[2];
    const float* bias_table = (const float*)d_in[3];
    const float* w_proj     = (const float*)d_in[4];
    const float* b_proj     = (const float*)d_in[5];
    const float* g1         = (const float*)d_in[6];
    const float* be1        = (const float*)d_in[7];
    const float* w_fc1      = (const float*)d_in[8];
    const float* b_fc1      = (const float*)d_in[9];
    const float* w_fc2      = (const float*)d_in[10];
    const float* b_fc2      = (const float*)d_in[11];
    const float* g2         = (const float*)d_in[12];
    const float* be2        = (const float*)d_in[13];
    const int*   rel_index  = (const int*)d_in[14];
    const float* attn_mask  = (const float*)d_in[15];
    float* out = (float*)d_out;

    cudaFuncSetAttribute(qkv_mma_kernel, cudaFuncAttributeMaxDynamicSharedMemorySize,
                         GEMM_SMEM_BYTES);
    cudaFuncSetAttribute(proj_mma_kernel, cudaFuncAttributeMaxDynamicSharedMemorySize,
                         GEMM_SMEM_BYTES);
    cudaFuncSetAttribute(mlp_mma_kernel, cudaFuncAttributeMaxDynamicSharedMemorySize,
                         MLP_SMEM_BYTES);

    qkv_mma_kernel<<<dim3(3, M_TOTAL / 128), 256, GEMM_SMEM_BYTES>>>(x, w_qkv, b_qkv);
    attn_kernel<<<dim3(4096, 4), 128>>>(bias_table, rel_index, attn_mask);
    proj_mma_kernel<<<M_TOTAL / 128, 256, GEMM_SMEM_BYTES>>>(x, w_proj, b_proj, g1, be1, out);
    mlp_mma_kernel<<<M_TOTAL / 128, 256, MLP_SMEM_BYTES>>>(
        w_fc1, b_fc1, w_fc2, b_fc2, g2, be2, out);
}

// round 6
// speedup vs baseline: 1.6328x; 1.1437x over previous
#include <cuda_runtime.h>
#include <cstdint>

#define Bsz 16
#define HW 16384          // H*W per batch
#define Cdim 128
#define QKVN 384
#define NHEADS 4
#define HDp 32
#define SHIFT 4
#define EPSLN 1e-3f
#define SCALEQ 0.17677669529663689f
#define M_TOTAL (Bsz * HW)   // 262144 rows

// ---- scratch (static device globals; no runtime allocation) ----
__device__ float g_qkv[(size_t)M_TOTAL * QKVN];   // ~402 MB
__device__ float g_att[(size_t)M_TOTAL * Cdim];   // ~134 MB
__device__ float g_pb[(size_t)256 * NHEADS * 4096]; // combined relpos-bias + mask, 16 MB

// row m (window-ordered) -> source/dest token index in (B, H*W) layout
__device__ __forceinline__ int win_row_to_token(int m) {
    int b   = m >> 14;
    int r   = m & 16383;
    int win = r >> 6;
    int n   = r & 63;
    int hb  = win >> 4;
    int wb  = win & 15;
    int h   = ((hb << 3) + (n >> 3) + SHIFT) & 127;
    int w   = ((wb << 3) + (n & 7) + SHIFT) & 127;
    return (b << 14) + (h << 7) + w;
}

// ===================== warp-MMA (tf32) helpers =====================
__device__ __forceinline__ float to_tf32(float x) {
    float y;
    asm("cvt.rna.tf32.f32 %0, %1;" : "=f"(y) : "f"(x));
    return y;
}
__device__ __forceinline__ uint32_t fbits(float x) { return __float_as_uint(x); }

// D += A(16x8) * B(8x8), tf32 inputs, f32 accum
__device__ __forceinline__ void mma168(float* c, const uint32_t* a, const uint32_t* b) {
    asm volatile(
        "mma.sync.aligned.m16n8k8.row.col.f32.tf32.tf32.f32 "
        "{%0,%1,%2,%3}, {%4,%5,%6,%7}, {%8,%9}, {%0,%1,%2,%3};"
        : "+f"(c[0]), "+f"(c[1]), "+f"(c[2]), "+f"(c[3])
        : "r"(a[0]), "r"(a[1]), "r"(a[2]), "r"(a[3]), "r"(b[0]), "r"(b[1]));
}

// shared pitches (conflict-free, proven in R4 mlp kernel)
#define PAQ 132
#define PBQ 136
#define GEMM_SMEM_BYTES ((128 * PAQ + 128 * PBQ) * 4)

// ============================================================
// Kernel A: QKV GEMM, warp-MMA tf32, gathered A rows.
// ============================================================
__global__ __launch_bounds__(256, 1) void qkv_mma_kernel(
    const float* __restrict__ x, const float* __restrict__ wq,
    const float* __restrict__ bias) {
    extern __shared__ float sm[];
    float* As = sm;               // 128 x PAQ
    float* Bs = As + 128 * PAQ;   // 128 x PBQ

    const int tid  = threadIdx.x;
    const int w    = tid >> 5;
    const int lane = tid & 31;
    const int mbase = blockIdx.y << 7;
    const int nbase = blockIdx.x << 7;

    const int base_m = (w >> 1) << 5;
    const int base_n = (w & 1) << 6;

    for (int i = tid; i < 4096; i += 256) {
        int r = i >> 5, c4 = (i & 31) << 2;
        float4 v = *(const float4*)(x + (size_t)win_row_to_token(mbase + r) * Cdim + c4);
        float* p = As + r * PAQ + c4;
        p[0] = to_tf32(v.x); p[1] = to_tf32(v.y);
        p[2] = to_tf32(v.z); p[3] = to_tf32(v.w);
    }
    for (int i = tid; i < 4096; i += 256) {
        int k = i >> 5, n4 = (i & 31) << 2;
        float4 v = *(const float4*)(wq + (size_t)k * QKVN + nbase + n4);
        float* p = Bs + k * PBQ + n4;
        p[0] = to_tf32(v.x); p[1] = to_tf32(v.y);
        p[2] = to_tf32(v.z); p[3] = to_tf32(v.w);
    }
    __syncthreads();

    float c2[2][8][4];
#pragma unroll
    for (int mt = 0; mt < 2; mt++)
#pragma unroll
        for (int nt = 0; nt < 8; nt++)
#pragma unroll
            for (int j = 0; j < 4; j++) c2[mt][nt][j] = 0.f;

    const int ar = lane >> 2, ac = lane & 3;
    const int bn = base_n + (lane >> 2);
#pragma unroll
    for (int k0 = 0; k0 < 128; k0 += 8) {
        uint32_t a[2][4];
#pragma unroll
        for (int mt = 0; mt < 2; mt++) {
            const float* p = As + (base_m + (mt << 4) + ar) * PAQ + k0 + ac;
            a[mt][0] = fbits(p[0]);
            a[mt][1] = fbits(p[8 * PAQ]);
            a[mt][2] = fbits(p[4]);
            a[mt][3] = fbits(p[8 * PAQ + 4]);
        }
        uint32_t b[8][2];
#pragma unroll
        for (int nt = 0; nt < 8; nt++) {
            const float* p = Bs + (k0 + ac) * PBQ + bn + (nt << 3);
            b[nt][0] = fbits(p[0]);
            b[nt][1] = fbits(p[4 * PBQ]);
        }
#pragma unroll
        for (int mt = 0; mt < 2; mt++)
#pragma unroll
            for (int nt = 0; nt < 8; nt++)
                mma168(c2[mt][nt], a[mt], b[nt]);
    }

#pragma unroll
    for (int mt = 0; mt < 2; mt++) {
        int r0 = base_m + (mt << 4) + (lane >> 2);
#pragma unroll
        for (int nt = 0; nt < 8; nt++) {
            int col = base_n + (nt << 3) + ((lane & 3) << 1);
            float bb0 = __ldg(&bias[nbase + col]);
            float bb1 = __ldg(&bias[nbase + col + 1]);
#pragma unroll
            for (int half = 0; half < 2; half++) {
                int r = r0 + half * 8;
                float2 o = make_float2(c2[mt][nt][half * 2 + 0] + bb0,
                                       c2[mt][nt][half * 2 + 1] + bb1);
                *(float2*)&g_qkv[(size_t)(mbase + r) * QKVN + nbase + col] = o;
            }
        }
    }
}

// ============================================================
// Kernel PB: combined relative-position-bias + shift mask table.
// g_pb[wimg][head][n][m] = bias_table[rel_index[n*64+m]*4+head] + mask[wimg][n*64+m]
// ============================================================
__global__ __launch_bounds__(256) void pb_kernel(
    const float* __restrict__ bt, const int* __restrict__ ri,
    const float* __restrict__ mask) {
    const int wimg = blockIdx.x, head = blockIdx.y;
    const float* mrow = mask + (size_t)wimg * 4096;
    float* out = g_pb + ((size_t)(wimg * NHEADS + head)) * 4096;
    for (int i = threadIdx.x; i < 4096; i += 256)
        out[i] = __ldg(&bt[ri[i] * NHEADS + head]) + mrow[i];
}

// ============================================================
// Kernel B: windowed attention, warp-MMA tf32.
// CTA = 2 windows, 256 threads, warp = (window, head).
// Per warp: 4 row-chunks of 16; S[16x64] mma -> +pb -> softmax ->
// P (tf32, smem) -> P@V mma -> O[16x32] -> g_att.
// K/V in smem [64][36] natural layout (col-B fragment of K^T reads it
// directly, bank-conflict-free). P pitch 68.
// ============================================================
#define PSK 36
#define PSP 68
#define ATT_SMEM_BYTES ((8 * 64 * PSK * 2 + 8 * 16 * PSP) * 4)

__global__ __launch_bounds__(256, 1) void attn_mma_kernel() {
    extern __shared__ float sm[];
    float* ks = sm;                    // [8][64][PSK]
    float* vs = ks + 8 * 64 * PSK;     // [8][64][PSK]
    float* Ps = vs + 8 * 64 * PSK;     // [8][16][PSP]

    const int tid  = threadIdx.x;
    const int w    = tid >> 5;
    const int lane = tid & 31;
    const int win0 = blockIdx.x << 1;

    // ---- stage K and V (tf32) for both windows, all heads ----
    for (int i = tid; i < 4096; i += 256) {
        int slot = i >> 9;            // 0..7 : (winlocal<<2) + head
        int rem  = i & 511;
        int m    = rem >> 3;
        int d4   = (rem & 7) << 2;
        int wn   = win0 + (slot >> 2), hd = slot & 3;
        const float* p = g_qkv + ((size_t)(wn * 64 + m)) * QKVN + 128 + hd * HDp + d4;
        float4 kv = *(const float4*)p;
        float4 vv = *(const float4*)(p + 128);
        float* kp = ks + slot * 64 * PSK + m * PSK + d4;
        kp[0] = to_tf32(kv.x); kp[1] = to_tf32(kv.y);
        kp[2] = to_tf32(kv.z); kp[3] = to_tf32(kv.w);
        float* vp = vs + slot * 64 * PSK + m * PSK + d4;
        vp[0] = to_tf32(vv.x); vp[1] = to_tf32(vv.y);
        vp[2] = to_tf32(vv.z); vp[3] = to_tf32(vv.w);
    }
    __syncthreads();

    const int win  = win0 + (w >> 2);
    const int head = w & 3;
    const int wimg = win & 255;
    const float* qbase = g_qkv + ((size_t)win * 64) * QKVN + head * HDp;
    const float* pbb   = g_pb + ((size_t)(wimg * NHEADS + head)) * 4096;
    float* kp = ks + w * 64 * PSK;
    float* vp = vs + w * 64 * PSK;
    float* pp = Ps + w * 16 * PSP;

    const int gr = lane >> 2, ac = lane & 3;

    for (int ch = 0; ch < 4; ch++) {
        const int r0 = ch << 4;

        // ---- S = (Q*scale) @ K^T : c1[8][4] ----
        float c1[8][4];
#pragma unroll
        for (int nt = 0; nt < 8; nt++)
#pragma unroll
            for (int j = 0; j < 4; j++) c1[nt][j] = 0.f;

#pragma unroll
        for (int k0 = 0; k0 < 32; k0 += 8) {
            uint32_t a[4];
            const float* q0 = qbase + (size_t)(r0 + gr) * QKVN + k0 + ac;
            a[0] = fbits(to_tf32(q0[0] * SCALEQ));
            a[1] = fbits(to_tf32(q0[8 * QKVN] * SCALEQ));
            a[2] = fbits(to_tf32(q0[4] * SCALEQ));
            a[3] = fbits(to_tf32(q0[8 * QKVN + 4] * SCALEQ));
            uint32_t b[8][2];
#pragma unroll
            for (int nt = 0; nt < 8; nt++) {
                const float* kb = kp + ((nt << 3) + gr) * PSK + k0 + ac;
                b[nt][0] = fbits(kb[0]);
                b[nt][1] = fbits(kb[4]);
            }
#pragma unroll
            for (int nt = 0; nt < 8; nt++) mma168(c1[nt], a, b[nt]);
        }

        // ---- + (bias+mask), softmax over the 64 keys ----
        float mx0 = -1e30f, mx1 = -1e30f;
#pragma unroll
        for (int nt = 0; nt < 8; nt++) {
            int col = (ac << 1) + (nt << 3);
            float2 p0 = *(const float2*)(pbb + (r0 + gr) * 64 + col);
            float2 p1 = *(const float2*)(pbb + (r0 + gr + 8) * 64 + col);
            c1[nt][0] += p0.x; c1[nt][1] += p0.y;
            c1[nt][2] += p1.x; c1[nt][3] += p1.y;
            mx0 = fmaxf(mx0, fmaxf(c1[nt][0], c1[nt][1]));
            mx1 = fmaxf(mx1, fmaxf(c1[nt][2], c1[nt][3]));
        }
        mx0 = fmaxf(mx0, __shfl_xor_sync(0xffffffffu, mx0, 1));
        mx0 = fmaxf(mx0, __shfl_xor_sync(0xffffffffu, mx0, 2));
        mx1 = fmaxf(mx1, __shfl_xor_sync(0xffffffffu, mx1, 1));
        mx1 = fmaxf(mx1, __shfl_xor_sync(0xffffffffu, mx1, 2));
        float s0 = 0.f, s1 = 0.f;
#pragma unroll
        for (int nt = 0; nt < 8; nt++) {
            c1[nt][0] = __expf(c1[nt][0] - mx0);
            c1[nt][1] = __expf(c1[nt][1] - mx0);
            c1[nt][2] = __expf(c1[nt][2] - mx1);
            c1[nt][3] = __expf(c1[nt][3] - mx1);
            s0 += c1[nt][0] + c1[nt][1];
            s1 += c1[nt][2] + c1[nt][3];
        }
        s0 += __shfl_xor_sync(0xffffffffu, s0, 1);
        s0 += __shfl_xor_sync(0xffffffffu, s0, 2);
        s1 += __shfl_xor_sync(0xffffffffu, s1, 1);
        s1 += __shfl_xor_sync(0xffffffffu, s1, 2);
        float i0 = 1.0f / s0, i1 = 1.0f / s1;

        __syncwarp();
#pragma unroll
        for (int nt = 0; nt < 8; nt++) {
            int col = (ac << 1) + (nt << 3);
            pp[gr * PSP + col]           = to_tf32(c1[nt][0] * i0);
            pp[gr * PSP + col + 1]       = to_tf32(c1[nt][1] * i0);
            pp[(gr + 8) * PSP + col]     = to_tf32(c1[nt][2] * i1);
            pp[(gr + 8) * PSP + col + 1] = to_tf32(c1[nt][3] * i1);
        }
        __syncwarp();

        // ---- O = P @ V : co[4][4] ----
        float co[4][4];
#pragma unroll
        for (int nt = 0; nt < 4; nt++)
#pragma unroll
            for (int j = 0; j < 4; j++) co[nt][j] = 0.f;

#pragma unroll
        for (int k0 = 0; k0 < 64; k0 += 8) {
            uint32_t a[4];
            const float* pa = pp + gr * PSP + k0 + ac;
            a[0] = fbits(pa[0]);
            a[1] = fbits(pa[8 * PSP]);
            a[2] = fbits(pa[4]);
            a[3] = fbits(pa[8 * PSP + 4]);
            uint32_t b[4][2];
#pragma unroll
            for (int nt = 0; nt < 4; nt++) {
                const float* vb = vp + ((k0 + ac)) * PSK + (nt << 3) + gr;
                b[nt][0] = fbits(vb[0]);
                b[nt][1] = fbits(vb[4 * PSK]);
            }
#pragma unroll
            for (int nt = 0; nt < 4; nt++) mma168(co[nt], a, b[nt]);
        }

        // ---- store O chunk ----
        float* ob0 = g_att + ((size_t)(win * 64 + r0 + gr)) * Cdim + head * HDp;
        float* ob1 = g_att + ((size_t)(win * 64 + r0 + gr + 8)) * Cdim + head * HDp;
#pragma unroll
        for (int nt = 0; nt < 4; nt++) {
            int col = (ac << 1) + (nt << 3);
            *(float2*)(ob0 + col) = make_float2(co[nt][0], co[nt][1]);
            *(float2*)(ob1 + col) = make_float2(co[nt][2], co[nt][3]);
        }
        __syncwarp();
    }
}

// ============================================================
// Kernel C: proj GEMM (warp-MMA tf32) + window-reverse/unshift + LN + residual.
// ============================================================
__global__ __launch_bounds__(256, 1) void proj_mma_kernel(
    const float* __restrict__ x, const float* __restrict__ wp_g,
    const float* __restrict__ bp, const float* __restrict__ g1,
    const float* __restrict__ be1, float* __restrict__ out) {
    extern __shared__ float sm[];
    float* As = sm;
    float* Bs = As + 128 * PAQ;

    const int tid  = threadIdx.x;
    const int w    = tid >> 5;
    const int lane = tid & 31;
    const int mbase = blockIdx.x << 7;

    const int base_m = (w >> 1) << 5;
    const int base_n = (w & 1) << 6;

    for (int i = tid; i < 4096; i += 256) {
        int r = i >> 5, c4 = (i & 31) << 2;
        float4 v = *(const float4*)(g_att + (((size_t)(mbase + r)) << 7) + c4);
        float* p = As + r * PAQ + c4;
        p[0] = to_tf32(v.x); p[1] = to_tf32(v.y);
        p[2] = to_tf32(v.z); p[3] = to_tf32(v.w);
    }
    for (int i = tid; i < 4096; i += 256) {
        int k = i >> 5, n4 = (i & 31) << 2;
        float4 v = *(const float4*)(wp_g + (size_t)k * Cdim + n4);
        float* p = Bs + k * PBQ + n4;
        p[0] = to_tf32(v.x); p[1] = to_tf32(v.y);
        p[2] = to_tf32(v.z); p[3] = to_tf32(v.w);
    }
    __syncthreads();

    float c2[2][8][4];
#pragma unroll
    for (int mt = 0; mt < 2; mt++)
#pragma unroll
        for (int nt = 0; nt < 8; nt++)
#pragma unroll
            for (int j = 0; j < 4; j++) c2[mt][nt][j] = 0.f;

    const int ar = lane >> 2, ac = lane & 3;
    const int bn = base_n + (lane >> 2);
#pragma unroll
    for (int k0 = 0; k0 < 128; k0 += 8) {
        uint32_t a[2][4];
#pragma unroll
        for (int mt = 0; mt < 2; mt++) {
            const float* p = As + (base_m + (mt << 4) + ar) * PAQ + k0 + ac;
            a[mt][0] = fbits(p[0]);
            a[mt][1] = fbits(p[8 * PAQ]);
            a[mt][2] = fbits(p[4]);
            a[mt][3] = fbits(p[8 * PAQ + 4]);
        }
        uint32_t b[8][2];
#pragma unroll
        for (int nt = 0; nt < 8; nt++) {
            const float* p = Bs + (k0 + ac) * PBQ + bn + (nt << 3);
            b[nt][0] = fbits(p[0]);
            b[nt][1] = fbits(p[4 * PBQ]);
        }
#pragma unroll
        for (int mt = 0; mt < 2; mt++)
#pragma unroll
            for (int nt = 0; nt < 8; nt++)
                mma168(c2[mt][nt], a[mt], b[nt]);
    }

    __syncthreads();
    float* ob = Bs;
#pragma unroll
    for (int mt = 0; mt < 2; mt++) {
        int r0 = base_m + (mt << 4) + (lane >> 2);
#pragma unroll
        for (int nt = 0; nt < 8; nt++) {
            int col = base_n + (nt << 3) + ((lane & 3) << 1);
            float bb0 = __ldg(&bp[col]);
            float bb1 = __ldg(&bp[col + 1]);
#pragma unroll
            for (int half = 0; half < 2; half++) {
                int r = r0 + half * 8;
                ob[r * PAQ + col]     = c2[mt][nt][half * 2 + 0] + bb0;
                ob[r * PAQ + col + 1] = c2[mt][nt][half * 2 + 1] + bb1;
            }
        }
    }
    __syncthreads();

    {
        int r   = tid >> 1;
        int h64 = (tid & 1) << 6;
        float s1 = 0.f, s2 = 0.f;
#pragma unroll
        for (int j = 0; j < 64; j += 4) {
            float4 v = *(float4*)&ob[r * PAQ + h64 + j];
            s1 += v.x + v.y + v.z + v.w;
            s2 += v.x * v.x + v.y * v.y + v.z * v.z + v.w * v.w;
        }
        s1 += __shfl_xor_sync(0xffffffffu, s1, 1);
        s2 += __shfl_xor_sync(0xffffffffu, s2, 1);
        float mean = s1 * (1.0f / 128.0f);
        float var  = s2 * (1.0f / 128.0f) - mean * mean;
        float rs   = rsqrtf(var + EPSLN);
        size_t rowoff = ((size_t)win_row_to_token(mbase + r)) << 7;
#pragma unroll
        for (int j = 0; j < 64; j += 4) {
            int cc = h64 + j;
            float4 v  = *(float4*)&ob[r * PAQ + cc];
            float4 xr = *(const float4*)(x + rowoff + cc);
            float4 gg = *(const float4*)(g1 + cc);
            float4 bb = *(const float4*)(be1 + cc);
            float4 o;
            o.x = xr.x + (v.x - mean) * rs * gg.x + bb.x;
            o.y = xr.y + (v.y - mean) * rs * gg.y + bb.y;
            o.z = xr.z + (v.z - mean) * rs * gg.z + bb.z;
            o.w = xr.w + (v.w - mean) * rs * gg.w + bb.w;
            *(float4*)(out + rowoff + cc) = o;
        }
    }
}

// ============================================================
// Kernel D: tf32 warp-MMA MLP (unchanged from R4).
// ============================================================
#define PA  132
#define PB1 72
#define PH  68
#define PW2 136
#define MLP_SMEM_FLOATS (128 * PA + 128 * PB1 + 128 * PH + 64 * PW2)
#define MLP_SMEM_BYTES  (MLP_SMEM_FLOATS * 4)

__global__ __launch_bounds__(256, 1) void mlp_mma_kernel(
    const float* __restrict__ w1g, const float* __restrict__ b1,
    const float* __restrict__ w2g, const float* __restrict__ b2,
    const float* __restrict__ g2v, const float* __restrict__ be2v,
    float* __restrict__ io) {
    extern __shared__ float sm[];
    float* As  = sm;
    float* Bs  = As + 128 * PA;
    float* Hs  = Bs + 128 * PB1;
    float* W2s = Hs + 128 * PH;

    const int tid  = threadIdx.x;
    const int w    = tid >> 5;
    const int lane = tid & 31;
    const int mbase = blockIdx.x << 7;

    const int base_m  = (w >> 1) << 5;
    const int base_n1 = (w & 1) << 5;
    const int base_n2 = (w & 1) << 6;

    for (int i = tid; i < 4096; i += 256) {
        int r = i >> 5, c4 = (i & 31) << 2;
        float4 v = *(const float4*)(io + (((size_t)(mbase + r)) << 7) + c4);
        float* p = As + r * PA + c4;
        p[0] = to_tf32(v.x); p[1] = to_tf32(v.y);
        p[2] = to_tf32(v.z); p[3] = to_tf32(v.w);
    }

    float c2[2][8][4];
#pragma unroll
    for (int mt = 0; mt < 2; mt++)
#pragma unroll
        for (int nt = 0; nt < 8; nt++)
#pragma unroll
            for (int j = 0; j < 4; j++) c2[mt][nt][j] = 0.f;

    for (int c = 0; c < 8; ++c) {
        __syncthreads();
        for (int i = tid; i < 2048; i += 256) {
            int k = i >> 4, n4 = (i & 15) << 2;
            float4 v = *(const float4*)(w1g + (size_t)k * 512 + (c << 6) + n4);
            float* p = Bs + k * PB1 + n4;
            p[0] = to_tf32(v.x); p[1] = to_tf32(v.y);
            p[2] = to_tf32(v.z); p[3] = to_tf32(v.w);
        }
        for (int i = tid; i < 2048; i += 256) {
            int k = i >> 5, n4 = (i & 31) << 2;
            float4 v = *(const float4*)(w2g + (((size_t)((c << 6) + k)) << 7) + n4);
            float* p = W2s + k * PW2 + n4;
            p[0] = to_tf32(v.x); p[1] = to_tf32(v.y);
            p[2] = to_tf32(v.z); p[3] = to_tf32(v.w);
        }
        __syncthreads();

        float c1[2][4][4];
#pragma unroll
        for (int mt = 0; mt < 2; mt++)
#pragma unroll
            for (int nt = 0; nt < 4; nt++)
#pragma unroll
                for (int j = 0; j < 4; j++) c1[mt][nt][j] = 0.f;

        const int ar = lane >> 2, ac = lane & 3;
        const int bn = base_n1 + (lane >> 2);
#pragma unroll
        for (int k0 = 0; k0 < 128; k0 += 8) {
            uint32_t a[2][4];
#pragma unroll
            for (int mt = 0; mt < 2; mt++) {
                const float* p = As + (base_m + (mt << 4) + ar) * PA + k0 + ac;
                a[mt][0] = fbits(p[0]);
                a[mt][1] = fbits(p[8 * PA]);
                a[mt][2] = fbits(p[4]);
                a[mt][3] = fbits(p[8 * PA + 4]);
            }
            uint32_t b[4][2];
#pragma unroll
            for (int nt = 0; nt < 4; nt++) {
                const float* p = Bs + (k0 + ac) * PB1 + bn + (nt << 3);
                b[nt][0] = fbits(p[0]);
                b[nt][1] = fbits(p[4 * PB1]);
            }
#pragma unroll
            for (int mt = 0; mt < 2; mt++)
#pragma unroll
                for (int nt = 0; nt < 4; nt++)
                    mma168(c1[mt][nt], a[mt], b[nt]);
        }

#pragma unroll
        for (int mt = 0; mt < 2; mt++) {
            int r0 = base_m + (mt << 4) + (lane >> 2);
#pragma unroll
            for (int nt = 0; nt < 4; nt++) {
                int col = base_n1 + (nt << 3) + ((lane & 3) << 1);
                float bb0 = __ldg(&b1[(c << 6) + col]);
                float bb1 = __ldg(&b1[(c << 6) + col + 1]);
#pragma unroll
                for (int half = 0; half < 2; half++) {
                    int r = r0 + half * 8;
                    float v0 = c1[mt][nt][half * 2 + 0] + bb0;
                    float v1 = c1[mt][nt][half * 2 + 1] + bb1;
                    v0 = 0.5f * v0 * (1.0f + erff(v0 * 0.70710678118654752f));
                    v1 = 0.5f * v1 * (1.0f + erff(v1 * 0.70710678118654752f));
                    Hs[r * PH + col]     = to_tf32(v0);
                    Hs[r * PH + col + 1] = to_tf32(v1);
                }
            }
        }
        __syncthreads();

        const int bn2 = base_n2 + (lane >> 2);
#pragma unroll
        for (int k0 = 0; k0 < 64; k0 += 8) {
            uint32_t a[2][4];
#pragma unroll
            for (int mt = 0; mt < 2; mt++) {
                const float* p = Hs + (base_m + (mt << 4) + ar) * PH + k0 + ac;
                a[mt][0] = fbits(p[0]);
                a[mt][1] = fbits(p[8 * PH]);
                a[mt][2] = fbits(p[4]);
                a[mt][3] = fbits(p[8 * PH + 4]);
            }
            uint32_t b[8][2];
#pragma unroll
            for (int nt = 0; nt < 8; nt++) {
                const float* p = W2s + (k0 + ac) * PW2 + bn2 + (nt << 3);
                b[nt][0] = fbits(p[0]);
                b[nt][1] = fbits(p[4 * PW2]);
            }
#pragma unroll
            for (int mt = 0; mt < 2; mt++)
#pragma unroll
                for (int nt = 0; nt < 8; nt++)
                    mma168(c2[mt][nt], a[mt], b[nt]);
        }
    }

    __syncthreads();
    float* ob = Bs;
#pragma unroll
    for (int mt = 0; mt < 2; mt++) {
        int r0 = base_m + (mt << 4) + (lane >> 2);
#pragma unroll
        for (int nt = 0; nt < 8; nt++) {
            int col = base_n2 + (nt << 3) + ((lane & 3) << 1);
            float bb0 = __ldg(&b2[col]);
            float bb1 = __ldg(&b2[col + 1]);
#pragma unroll
            for (int half = 0; half < 2; half++) {
                int r = r0 + half * 8;
                ob[r * PA + col]     = c2[mt][nt][half * 2 + 0] + bb0;
                ob[r * PA + col + 1] = c2[mt][nt][half * 2 + 1] + bb1;
            }
        }
    }
    __syncthreads();

    {
        int r   = tid >> 1;
        int h64 = (tid & 1) << 6;
        float s1 = 0.f, s2 = 0.f;
#pragma unroll
        for (int j = 0; j < 64; j += 4) {
            float4 v = *(float4*)&ob[r * PA + h64 + j];
            s1 += v.x + v.y + v.z + v.w;
            s2 += v.x * v.x + v.y * v.y + v.z * v.z + v.w * v.w;
        }
        s1 += __shfl_xor_sync(0xffffffffu, s1, 1);
        s2 += __shfl_xor_sync(0xffffffffu, s2, 1);
        float mean = s1 * (1.0f / 128.0f);
        float var  = s2 * (1.0f / 128.0f) - mean * mean;
        float rs   = rsqrtf(var + EPSLN);
        size_t rowoff = ((size_t)(mbase + r)) << 7;
#pragma unroll
        for (int j = 0; j < 64; j += 4) {
            int cc = h64 + j;
            float4 v  = *(float4*)&ob[r * PA + cc];
            float4 xr = *(const float4*)(io + rowoff + cc);
            float4 gg = *(const float4*)(g2v + cc);
            float4 bb = *(const float4*)(be2v + cc);
            float4 o;
            o.x = xr.x + (v.x - mean) * rs * gg.x + bb.x;
            o.y = xr.y + (v.y - mean) * rs * gg.y + bb.y;
            o.z = xr.z + (v.z - mean) * rs * gg.z + bb.z;
            o.w = xr.w + (v.w - mean) * rs * gg.w + bb.w;
            *(float4*)(io + rowoff + cc) = o;
        }
    }
}

// ============================================================
extern "C" void kernel_launch(void* const* d_in, const int* in_sizes, int n_in,
                              void* d_out, int out_size) {
    const float* x          = (const float*)d_in[0];
    const float* w_qkv      = (const float*)d_in[1];
    const float* b_qkv      = (const float*)d_in[2];
    const float* bias_table = (const float*)d_in[3];
    const float* w_proj     = (const float*)d_in[4];
    const float* b_proj     = (const float*)d_in[5];
    const float* g1         = (const float*)d_in[6];
    const float* be1        = (const float*)d_in[7];
    const float* w_fc1      = (const float*)d_in[8];
    const float* b_fc1      = (const float*)d_in[9];
    const float* w_fc2      = (const float*)d_in[10];
    const float* b_fc2      = (const float*)d_in[11];
    const float* g2         = (const float*)d_in[12];
    const float* be2        = (const float*)d_in[13];
    const int*   rel_index  = (const int*)d_in[14];
    const float* attn_mask  = (const float*)d_in[15];
    float* out = (float*)d_out;

    cudaFuncSetAttribute(qkv_mma_kernel, cudaFuncAttributeMaxDynamicSharedMemorySize,
                         GEMM_SMEM_BYTES);
    cudaFuncSetAttribute(attn_mma_kernel, cudaFuncAttributeMaxDynamicSharedMemorySize,
                         ATT_SMEM_BYTES);
    cudaFuncSetAttribute(proj_mma_kernel, cudaFuncAttributeMaxDynamicSharedMemorySize,
                         GEMM_SMEM_BYTES);
    cudaFuncSetAttribute(mlp_mma_kernel, cudaFuncAttributeMaxDynamicSharedMemorySize,
                         MLP_SMEM_BYTES);

    qkv_mma_kernel<<<dim3(3, M_TOTAL / 128), 256, GEMM_SMEM_BYTES>>>(x, w_qkv, b_qkv);
    pb_kernel<<<dim3(256, NHEADS), 256>>>(bias_table, rel_index, attn_mask);
    attn_mma_kernel<<<M_TOTAL / 128, 256, ATT_SMEM_BYTES>>>();
    proj_mma_kernel<<<M_TOTAL / 128, 256, GEMM_SMEM_BYTES>>>(x, w_proj, b_proj, g1, be1, out);
    mlp_mma_kernel<<<M_TOTAL / 128, 256, MLP_SMEM_BYTES>>>(
        w_fc1, b_fc1, w_fc2, b_fc2, g2, be2, out);
}

// round 7
// speedup vs baseline: 2.1664x; 1.3268x over previous
#include <cuda_runtime.h>
#include <cstdint>

#define Bsz 16
#define HW 16384
#define Cdim 128
#define QKVN 384
#define NHEADS 4
#define HDp 32
#define SHIFT 4
#define EPSLN 1e-3f
#define SCALEQ 0.17677669529663689f
#define M_TOTAL (Bsz * HW)

// ---- scratch ----
__device__ float g_qkv[(size_t)M_TOTAL * QKVN];
__device__ float g_att[(size_t)M_TOTAL * Cdim];
__device__ float g_pb[(size_t)256 * NHEADS * 4096];

__device__ __forceinline__ int win_row_to_token(int m) {
    int b   = m >> 14;
    int r   = m & 16383;
    int win = r >> 6;
    int n   = r & 63;
    int hb  = win >> 4;
    int wb  = win & 15;
    int h   = ((hb << 3) + (n >> 3) + SHIFT) & 127;
    int w   = ((wb << 3) + (n & 7) + SHIFT) & 127;
    return (b << 14) + (h << 7) + w;
}

// ===================== helpers =====================
__device__ __forceinline__ float to_tf32(float x) {
    float y;
    asm("cvt.rna.tf32.f32 %0, %1;" : "=f"(y) : "f"(x));
    return y;
}
__device__ __forceinline__ uint32_t fbits(float x) { return __float_as_uint(x); }

__device__ __forceinline__ void mma168(float* c, const uint32_t* a, const uint32_t* b) {
    asm volatile(
        "mma.sync.aligned.m16n8k8.row.col.f32.tf32.tf32.f32 "
        "{%0,%1,%2,%3}, {%4,%5,%6,%7}, {%8,%9}, {%0,%1,%2,%3};"
        : "+f"(c[0]), "+f"(c[1]), "+f"(c[2]), "+f"(c[3])
        : "r"(a[0]), "r"(a[1]), "r"(a[2]), "r"(a[3]), "r"(b[0]), "r"(b[1]));
}

__device__ __forceinline__ uint32_t smem_u32(const void* p) {
    uint32_t a;
    asm("{ .reg .u64 t; cvta.to.shared.u64 t, %1; cvt.u32.u64 %0, t; }"
        : "=r"(a) : "l"(p));
    return a;
}
__device__ __forceinline__ void cp16(void* s, const void* g) {
    asm volatile("cp.async.ca.shared.global [%0], [%1], 16;"
                 :: "r"(smem_u32(s)), "l"(g));
}
#define CP_COMMIT() asm volatile("cp.async.commit_group;" ::: "memory")
#define CP_WAIT(n)  asm volatile("cp.async.wait_group %0;" :: "n"(n) : "memory")

// pitches: A-type must be ==4 (mod 32); B-type ==8 (mod 32)
#define PAQ 132
#define PBQ 136
#define GEMM_SMEM_BYTES ((64 * PAQ + 128 * PBQ) * 4)   // 101 KB -> 2 CTA/SM

// ============================================================
// Kernel A: QKV GEMM, M-tile 64, cp.async, 2 CTA/SM.
// grid (3, 4096). Warp = 16(M) x 64(N).
// ============================================================
__global__ __launch_bounds__(256, 2) void qkv_mma_kernel(
    const float* __restrict__ x, const float* __restrict__ wq,
    const float* __restrict__ bias) {
    extern __shared__ float sm[];
    float* As = sm;               // 64 x PAQ
    float* Bs = As + 64 * PAQ;    // 128 x PBQ

    const int tid  = threadIdx.x;
    const int w    = tid >> 5;
    const int lane = tid & 31;
    const int mbase = blockIdx.y << 6;
    const int nbase = blockIdx.x << 7;

    const int base_m = (w >> 1) << 4;
    const int base_n = (w & 1) << 6;

    for (int i = tid; i < 2048; i += 256) {
        int r = i >> 5, c4 = (i & 31) << 2;
        cp16(As + r * PAQ + c4,
             x + (size_t)win_row_to_token(mbase + r) * Cdim + c4);
    }
    for (int i = tid; i < 4096; i += 256) {
        int k = i >> 5, n4 = (i & 31) << 2;
        cp16(Bs + k * PBQ + n4, wq + (size_t)k * QKVN + nbase + n4);
    }
    CP_COMMIT();
    CP_WAIT(0);
    __syncthreads();

    float c2[8][4];
#pragma unroll
    for (int nt = 0; nt < 8; nt++)
#pragma unroll
        for (int j = 0; j < 4; j++) c2[nt][j] = 0.f;

    const int gr = lane >> 2, ac = lane & 3;
    const int bn = base_n + gr;
#pragma unroll
    for (int k0 = 0; k0 < 128; k0 += 8) {
        uint32_t a[4];
        {
            const float* p = As + (base_m + gr) * PAQ + k0 + ac;
            a[0] = fbits(p[0]);
            a[1] = fbits(p[8 * PAQ]);
            a[2] = fbits(p[4]);
            a[3] = fbits(p[8 * PAQ + 4]);
        }
        uint32_t b[8][2];
#pragma unroll
        for (int nt = 0; nt < 8; nt++) {
            const float* p = Bs + (k0 + ac) * PBQ + bn + (nt << 3);
            b[nt][0] = fbits(p[0]);
            b[nt][1] = fbits(p[4 * PBQ]);
        }
#pragma unroll
        for (int nt = 0; nt < 8; nt++) mma168(c2[nt], a, b[nt]);
    }

#pragma unroll
    for (int nt = 0; nt < 8; nt++) {
        int col = base_n + (nt << 3) + (ac << 1);
        float bb0 = __ldg(&bias[nbase + col]);
        float bb1 = __ldg(&bias[nbase + col + 1]);
        int r0 = base_m + gr;
        *(float2*)&g_qkv[(size_t)(mbase + r0) * QKVN + nbase + col] =
            make_float2(c2[nt][0] + bb0, c2[nt][1] + bb1);
        *(float2*)&g_qkv[(size_t)(mbase + r0 + 8) * QKVN + nbase + col] =
            make_float2(c2[nt][2] + bb0, c2[nt][3] + bb1);
    }
}

// ============================================================
// Kernel PB: combined relpos-bias + mask table.
// ============================================================
__global__ __launch_bounds__(256) void pb_kernel(
    const float* __restrict__ bt, const int* __restrict__ ri,
    const float* __restrict__ mask) {
    const int wimg = blockIdx.x, head = blockIdx.y;
    const float* mrow = mask + (size_t)wimg * 4096;
    float* out = g_pb + ((size_t)(wimg * NHEADS + head)) * 4096;
    for (int i = threadIdx.x; i < 4096; i += 256)
        out[i] = __ldg(&bt[ri[i] * NHEADS + head]) + mrow[i];
}

// ============================================================
// Kernel B: windowed attention, warp-MMA tf32 (unchanged from R6).
// ============================================================
#define PSK 36
#define PSP 68
#define ATT_SMEM_BYTES ((8 * 64 * PSK * 2 + 8 * 16 * PSP) * 4)

__global__ __launch_bounds__(256, 1) void attn_mma_kernel() {
    extern __shared__ float sm[];
    float* ks = sm;
    float* vs = ks + 8 * 64 * PSK;
    float* Ps = vs + 8 * 64 * PSK;

    const int tid  = threadIdx.x;
    const int w    = tid >> 5;
    const int lane = tid & 31;
    const int win0 = blockIdx.x << 1;

    for (int i = tid; i < 4096; i += 256) {
        int slot = i >> 9;
        int rem  = i & 511;
        int m    = rem >> 3;
        int d4   = (rem & 7) << 2;
        int wn   = win0 + (slot >> 2), hd = slot & 3;
        const float* p = g_qkv + ((size_t)(wn * 64 + m)) * QKVN + 128 + hd * HDp + d4;
        float4 kv = *(const float4*)p;
        float4 vv = *(const float4*)(p + 128);
        float* kp = ks + slot * 64 * PSK + m * PSK + d4;
        kp[0] = to_tf32(kv.x); kp[1] = to_tf32(kv.y);
        kp[2] = to_tf32(kv.z); kp[3] = to_tf32(kv.w);
        float* vp = vs + slot * 64 * PSK + m * PSK + d4;
        vp[0] = to_tf32(vv.x); vp[1] = to_tf32(vv.y);
        vp[2] = to_tf32(vv.z); vp[3] = to_tf32(vv.w);
    }
    __syncthreads();

    const int win  = win0 + (w >> 2);
    const int head = w & 3;
    const int wimg = win & 255;
    const float* qbase = g_qkv + ((size_t)win * 64) * QKVN + head * HDp;
    const float* pbb   = g_pb + ((size_t)(wimg * NHEADS + head)) * 4096;
    float* kp = ks + w * 64 * PSK;
    float* vp = vs + w * 64 * PSK;
    float* pp = Ps + w * 16 * PSP;

    const int gr = lane >> 2, ac = lane & 3;

    for (int ch = 0; ch < 4; ch++) {
        const int r0 = ch << 4;

        float c1[8][4];
#pragma unroll
        for (int nt = 0; nt < 8; nt++)
#pragma unroll
            for (int j = 0; j < 4; j++) c1[nt][j] = 0.f;

#pragma unroll
        for (int k0 = 0; k0 < 32; k0 += 8) {
            uint32_t a[4];
            const float* q0 = qbase + (size_t)(r0 + gr) * QKVN + k0 + ac;
            a[0] = fbits(to_tf32(q0[0] * SCALEQ));
            a[1] = fbits(to_tf32(q0[8 * QKVN] * SCALEQ));
            a[2] = fbits(to_tf32(q0[4] * SCALEQ));
            a[3] = fbits(to_tf32(q0[8 * QKVN + 4] * SCALEQ));
            uint32_t b[8][2];
#pragma unroll
            for (int nt = 0; nt < 8; nt++) {
                const float* kb = kp + ((nt << 3) + gr) * PSK + k0 + ac;
                b[nt][0] = fbits(kb[0]);
                b[nt][1] = fbits(kb[4]);
            }
#pragma unroll
            for (int nt = 0; nt < 8; nt++) mma168(c1[nt], a, b[nt]);
        }

        float mx0 = -1e30f, mx1 = -1e30f;
#pragma unroll
        for (int nt = 0; nt < 8; nt++) {
            int col = (ac << 1) + (nt << 3);
            float2 p0 = *(const float2*)(pbb + (r0 + gr) * 64 + col);
            float2 p1 = *(const float2*)(pbb + (r0 + gr + 8) * 64 + col);
            c1[nt][0] += p0.x; c1[nt][1] += p0.y;
            c1[nt][2] += p1.x; c1[nt][3] += p1.y;
            mx0 = fmaxf(mx0, fmaxf(c1[nt][0], c1[nt][1]));
            mx1 = fmaxf(mx1, fmaxf(c1[nt][2], c1[nt][3]));
        }
        mx0 = fmaxf(mx0, __shfl_xor_sync(0xffffffffu, mx0, 1));
        mx0 = fmaxf(mx0, __shfl_xor_sync(0xffffffffu, mx0, 2));
        mx1 = fmaxf(mx1, __shfl_xor_sync(0xffffffffu, mx1, 1));
        mx1 = fmaxf(mx1, __shfl_xor_sync(0xffffffffu, mx1, 2));
        float s0 = 0.f, s1 = 0.f;
#pragma unroll
        for (int nt = 0; nt < 8; nt++) {
            c1[nt][0] = __expf(c1[nt][0] - mx0);
            c1[nt][1] = __expf(c1[nt][1] - mx0);
            c1[nt][2] = __expf(c1[nt][2] - mx1);
            c1[nt][3] = __expf(c1[nt][3] - mx1);
            s0 += c1[nt][0] + c1[nt][1];
            s1 += c1[nt][2] + c1[nt][3];
        }
        s0 += __shfl_xor_sync(0xffffffffu, s0, 1);
        s0 += __shfl_xor_sync(0xffffffffu, s0, 2);
        s1 += __shfl_xor_sync(0xffffffffu, s1, 1);
        s1 += __shfl_xor_sync(0xffffffffu, s1, 2);
        float i0 = 1.0f / s0, i1 = 1.0f / s1;

        __syncwarp();
#pragma unroll
        for (int nt = 0; nt < 8; nt++) {
            int col = (ac << 1) + (nt << 3);
            pp[gr * PSP + col]           = to_tf32(c1[nt][0] * i0);
            pp[gr * PSP + col + 1]       = to_tf32(c1[nt][1] * i0);
            pp[(gr + 8) * PSP + col]     = to_tf32(c1[nt][2] * i1);
            pp[(gr + 8) * PSP + col + 1] = to_tf32(c1[nt][3] * i1);
        }
        __syncwarp();

        float co[4][4];
#pragma unroll
        for (int nt = 0; nt < 4; nt++)
#pragma unroll
            for (int j = 0; j < 4; j++) co[nt][j] = 0.f;

#pragma unroll
        for (int k0 = 0; k0 < 64; k0 += 8) {
            uint32_t a[4];
            const float* pa = pp + gr * PSP + k0 + ac;
            a[0] = fbits(pa[0]);
            a[1] = fbits(pa[8 * PSP]);
            a[2] = fbits(pa[4]);
            a[3] = fbits(pa[8 * PSP + 4]);
            uint32_t b[4][2];
#pragma unroll
            for (int nt = 0; nt < 4; nt++) {
                const float* vb = vp + ((k0 + ac)) * PSK + (nt << 3) + gr;
                b[nt][0] = fbits(vb[0]);
                b[nt][1] = fbits(vb[4 * PSK]);
            }
#pragma unroll
            for (int nt = 0; nt < 4; nt++) mma168(co[nt], a, b[nt]);
        }

        float* ob0 = g_att + ((size_t)(win * 64 + r0 + gr)) * Cdim + head * HDp;
        float* ob1 = g_att + ((size_t)(win * 64 + r0 + gr + 8)) * Cdim + head * HDp;
#pragma unroll
        for (int nt = 0; nt < 4; nt++) {
            int col = (ac << 1) + (nt << 3);
            *(float2*)(ob0 + col) = make_float2(co[nt][0], co[nt][1]);
            *(float2*)(ob1 + col) = make_float2(co[nt][2], co[nt][3]);
        }
        __syncwarp();
    }
}

// ============================================================
// Kernel C: proj GEMM, M-tile 64, cp.async, 2 CTA/SM + LN + residual.
// ============================================================
__global__ __launch_bounds__(256, 2) void proj_mma_kernel(
    const float* __restrict__ x, const float* __restrict__ wp_g,
    const float* __restrict__ bp, const float* __restrict__ g1,
    const float* __restrict__ be1, float* __restrict__ out) {
    extern __shared__ float sm[];
    float* As = sm;               // 64 x PAQ (later reused as ob)
    float* Bs = As + 64 * PAQ;    // 128 x PBQ

    const int tid  = threadIdx.x;
    const int w    = tid >> 5;
    const int lane = tid & 31;
    const int mbase = blockIdx.x << 6;

    const int base_m = (w >> 1) << 4;
    const int base_n = (w & 1) << 6;

    for (int i = tid; i < 2048; i += 256) {
        int r = i >> 5, c4 = (i & 31) << 2;
        cp16(As + r * PAQ + c4, g_att + (((size_t)(mbase + r)) << 7) + c4);
    }
    for (int i = tid; i < 4096; i += 256) {
        int k = i >> 5, n4 = (i & 31) << 2;
        cp16(Bs + k * PBQ + n4, wp_g + (size_t)k * Cdim + n4);
    }
    CP_COMMIT();
    CP_WAIT(0);
    __syncthreads();

    float c2[8][4];
#pragma unroll
    for (int nt = 0; nt < 8; nt++)
#pragma unroll
        for (int j = 0; j < 4; j++) c2[nt][j] = 0.f;

    const int gr = lane >> 2, ac = lane & 3;
    const int bn = base_n + gr;
#pragma unroll
    for (int k0 = 0; k0 < 128; k0 += 8) {
        uint32_t a[4];
        {
            const float* p = As + (base_m + gr) * PAQ + k0 + ac;
            a[0] = fbits(p[0]);
            a[1] = fbits(p[8 * PAQ]);
            a[2] = fbits(p[4]);
            a[3] = fbits(p[8 * PAQ + 4]);
        }
        uint32_t b[8][2];
#pragma unroll
        for (int nt = 0; nt < 8; nt++) {
            const float* p = Bs + (k0 + ac) * PBQ + bn + (nt << 3);
            b[nt][0] = fbits(p[0]);
            b[nt][1] = fbits(p[4 * PBQ]);
        }
#pragma unroll
        for (int nt = 0; nt < 8; nt++) mma168(c2[nt], a, b[nt]);
    }

    __syncthreads();   // done reading As; reuse as ob
    float* ob = As;
#pragma unroll
    for (int nt = 0; nt < 8; nt++) {
        int col = base_n + (nt << 3) + (ac << 1);
        float bb0 = __ldg(&bp[col]);
        float bb1 = __ldg(&bp[col + 1]);
        int r0 = base_m + gr;
        ob[r0 * PAQ + col]           = c2[nt][0] + bb0;
        ob[r0 * PAQ + col + 1]       = c2[nt][1] + bb1;
        ob[(r0 + 8) * PAQ + col]     = c2[nt][2] + bb0;
        ob[(r0 + 8) * PAQ + col + 1] = c2[nt][3] + bb1;
    }
    __syncthreads();

    {   // LN + residual + unshift scatter: 4 threads per row
        int r   = tid >> 2;
        int h32 = (tid & 3) << 5;
        float s1 = 0.f, s2 = 0.f;
#pragma unroll
        for (int j = 0; j < 32; j += 4) {
            float4 v = *(float4*)&ob[r * PAQ + h32 + j];
            s1 += v.x + v.y + v.z + v.w;
            s2 += v.x * v.x + v.y * v.y + v.z * v.z + v.w * v.w;
        }
        s1 += __shfl_xor_sync(0xffffffffu, s1, 1);
        s1 += __shfl_xor_sync(0xffffffffu, s1, 2);
        s2 += __shfl_xor_sync(0xffffffffu, s2, 1);
        s2 += __shfl_xor_sync(0xffffffffu, s2, 2);
        float mean = s1 * (1.0f / 128.0f);
        float var  = s2 * (1.0f / 128.0f) - mean * mean;
        float rs   = rsqrtf(var + EPSLN);
        size_t rowoff = ((size_t)win_row_to_token(mbase + r)) << 7;
#pragma unroll
        for (int j = 0; j < 32; j += 4) {
            int cc = h32 + j;
            float4 v  = *(float4*)&ob[r * PAQ + cc];
            float4 xr = *(const float4*)(x + rowoff + cc);
            float4 gg = *(const float4*)(g1 + cc);
            float4 bb = *(const float4*)(be1 + cc);
            float4 o;
            o.x = xr.x + (v.x - mean) * rs * gg.x + bb.x;
            o.y = xr.y + (v.y - mean) * rs * gg.y + bb.y;
            o.z = xr.z + (v.z - mean) * rs * gg.z + bb.z;
            o.w = xr.w + (v.w - mean) * rs * gg.w + bb.w;
            *(float4*)(out + rowoff + cc) = o;
        }
    }
}

// ============================================================
// Kernel D: tf32 warp-MMA MLP, slab=32, double-buffered cp.async weights.
// M=128, 256 threads. Pitches: A 132, W1 40, H 36, W2 136.
// ============================================================
#define PA   132
#define PW1  40
#define PH2  36
#define PW2B 136
#define MLP_A_F   (128 * PA)         // 16896
#define MLP_W1_F  (128 * PW1)        // 5120 per buf
#define MLP_H_F   (128 * PH2)        // 4608
#define MLP_W2_F  (32 * PW2B)        // 4352 per buf
#define MLP_SMEM_FLOATS (MLP_A_F + 2 * MLP_W1_F + MLP_H_F + 2 * MLP_W2_F)
#define MLP_SMEM_BYTES  (MLP_SMEM_FLOATS * 4)   // ~162 KB

__global__ __launch_bounds__(256, 1) void mlp_mma_kernel(
    const float* __restrict__ w1g, const float* __restrict__ b1,
    const float* __restrict__ w2g, const float* __restrict__ b2,
    const float* __restrict__ g2v, const float* __restrict__ be2v,
    float* __restrict__ io) {
    extern __shared__ float sm[];
    float* As  = sm;
    float* W1b = As + MLP_A_F;                 // [2][128][PW1]
    float* Hs  = W1b + 2 * MLP_W1_F;           // [128][PH2]
    float* W2b = Hs + MLP_H_F;                 // [2][32][PW2B]

    const int tid  = threadIdx.x;
    const int w    = tid >> 5;
    const int lane = tid & 31;
    const int mbase = blockIdx.x << 7;

    const int base_m  = (w >> 1) << 5;     // 32 rows per warp (2 mt of 16)
    const int base_n1 = (w & 1) << 4;      // fc1: 16 cols
    const int base_n2 = (w & 1) << 6;      // fc2: 64 cols

    const int gr = lane >> 2, ac = lane & 3;

    // group 0: A tile
    for (int i = tid; i < 4096; i += 256) {
        int r = i >> 5, c4 = (i & 31) << 2;
        cp16(As + r * PA + c4, io + (((size_t)(mbase + r)) << 7) + c4);
    }
    // group 0 also carries slab 0
    {
        float* w1d = W1b;
        for (int i = tid; i < 1024; i += 256) {
            int k = i >> 3, n4 = (i & 7) << 2;
            cp16(w1d + k * PW1 + n4, w1g + (size_t)k * 512 + n4);
        }
        float* w2d = W2b;
        for (int i = tid; i < 1024; i += 256) {
            int k = i >> 5, n4 = (i & 31) << 2;
            cp16(w2d + k * PW2B + n4, w2g + ((size_t)k << 7) + n4);
        }
    }
    CP_COMMIT();

    float c2[2][8][4];
#pragma unroll
    for (int mt = 0; mt < 2; mt++)
#pragma unroll
        for (int nt = 0; nt < 8; nt++)
#pragma unroll
            for (int j = 0; j < 4; j++) c2[mt][nt][j] = 0.f;

    for (int c = 0; c < 16; ++c) {
        // prefetch slab c+1
        if (c + 1 < 16) {
            float* w1d = W1b + ((c + 1) & 1) * MLP_W1_F;
            for (int i = tid; i < 1024; i += 256) {
                int k = i >> 3, n4 = (i & 7) << 2;
                cp16(w1d + k * PW1 + n4,
                     w1g + (size_t)k * 512 + ((c + 1) << 5) + n4);
            }
            float* w2d = W2b + ((c + 1) & 1) * MLP_W2_F;
            for (int i = tid; i < 1024; i += 256) {
                int k = i >> 5, n4 = (i & 31) << 2;
                cp16(w2d + k * PW2B + n4,
                     w2g + ((size_t)(((c + 1) << 5) + k) << 7) + n4);
            }
            CP_COMMIT();
            CP_WAIT(1);
        } else {
            CP_WAIT(0);
        }
        __syncthreads();   // slab c (and A) resident

        const float* w1s = W1b + (c & 1) * MLP_W1_F;
        const float* w2s = W2b + (c & 1) * MLP_W2_F;

        // ---- fc1: [128 x 32] slab, warp does 32 rows x 16 cols ----
        float c1[2][2][4];
#pragma unroll
        for (int mt = 0; mt < 2; mt++)
#pragma unroll
            for (int nt = 0; nt < 2; nt++)
#pragma unroll
                for (int j = 0; j < 4; j++) c1[mt][nt][j] = 0.f;

        const int bn1 = base_n1 + gr;
#pragma unroll
        for (int k0 = 0; k0 < 128; k0 += 8) {
            uint32_t a[2][4];
#pragma unroll
            for (int mt = 0; mt < 2; mt++) {
                const float* p = As + (base_m + (mt << 4) + gr) * PA + k0 + ac;
                a[mt][0] = fbits(p[0]);
                a[mt][1] = fbits(p[8 * PA]);
                a[mt][2] = fbits(p[4]);
                a[mt][3] = fbits(p[8 * PA + 4]);
            }
            uint32_t b[2][2];
#pragma unroll
            for (int nt = 0; nt < 2; nt++) {
                const float* p = w1s + (k0 + ac) * PW1 + bn1 + (nt << 3);
                b[nt][0] = fbits(p[0]);
                b[nt][1] = fbits(p[4 * PW1]);
            }
#pragma unroll
            for (int mt = 0; mt < 2; mt++)
#pragma unroll
                for (int nt = 0; nt < 2; nt++)
                    mma168(c1[mt][nt], a[mt], b[nt]);
        }

        // bias + exact GELU -> Hs
#pragma unroll
        for (int mt = 0; mt < 2; mt++) {
            int r0 = base_m + (mt << 4) + gr;
#pragma unroll
            for (int nt = 0; nt < 2; nt++) {
                int col = base_n1 + (nt << 3) + (ac << 1);
                float bb0 = __ldg(&b1[(c << 5) + col]);
                float bb1 = __ldg(&b1[(c << 5) + col + 1]);
#pragma unroll
                for (int half = 0; half < 2; half++) {
                    int r = r0 + half * 8;
                    float v0 = c1[mt][nt][half * 2 + 0] + bb0;
                    float v1 = c1[mt][nt][half * 2 + 1] + bb1;
                    v0 = 0.5f * v0 * (1.0f + erff(v0 * 0.70710678118654752f));
                    v1 = 0.5f * v1 * (1.0f + erff(v1 * 0.70710678118654752f));
                    Hs[r * PH2 + col]     = v0;
                    Hs[r * PH2 + col + 1] = v1;
                }
            }
        }
        __syncthreads();   // Hs visible

        // ---- fc2: acc += Hs[128x32] @ W2slab[32x128] ----
        const int bn2 = base_n2 + gr;
#pragma unroll
        for (int k0 = 0; k0 < 32; k0 += 8) {
            uint32_t a[2][4];
#pragma unroll
            for (int mt = 0; mt < 2; mt++) {
                const float* p = Hs + (base_m + (mt << 4) + gr) * PH2 + k0 + ac;
                a[mt][0] = fbits(p[0]);
                a[mt][1] = fbits(p[8 * PH2]);
                a[mt][2] = fbits(p[4]);
                a[mt][3] = fbits(p[8 * PH2 + 4]);
            }
            uint32_t b[8][2];
#pragma unroll
            for (int nt = 0; nt < 8; nt++) {
                const float* p = w2s + (k0 + ac) * PW2B + bn2 + (nt << 3);
                b[nt][0] = fbits(p[0]);
                b[nt][1] = fbits(p[4 * PW2B]);
            }
#pragma unroll
            for (int mt = 0; mt < 2; mt++)
#pragma unroll
                for (int nt = 0; nt < 8; nt++)
                    mma168(c2[mt][nt], a[mt], b[nt]);
        }
        __syncthreads();   // buf c / Hs reads complete before overwrite
    }

    // ---- epilogue: +b2 -> ob (reuse W1b..), LN, residual ----
    float* ob = W1b;   // 2*5120+4608+2*4352 = 23552 floats >= 16896
#pragma unroll
    for (int mt = 0; mt < 2; mt++) {
        int r0 = base_m + (mt << 4) + gr;
#pragma unroll
        for (int nt = 0; nt < 8; nt++) {
            int col = base_n2 + (nt << 3) + (ac << 1);
            float bb0 = __ldg(&b2[col]);
            float bb1 = __ldg(&b2[col + 1]);
#pragma unroll
            for (int half = 0; half < 2; half++) {
                int r = r0 + half * 8;
                ob[r * PA + col]     = c2[mt][nt][half * 2 + 0] + bb0;
                ob[r * PA + col + 1] = c2[mt][nt][half * 2 + 1] + bb1;
            }
        }
    }
    __syncthreads();

    {
        int r   = tid >> 1;
        int h64 = (tid & 1) << 6;
        float s1 = 0.f, s2 = 0.f;
#pragma unroll
        for (int j = 0; j < 64; j += 4) {
            float4 v = *(float4*)&ob[r * PA + h64 + j];
            s1 += v.x + v.y + v.z + v.w;
            s2 += v.x * v.x + v.y * v.y + v.z * v.z + v.w * v.w;
        }
        s1 += __shfl_xor_sync(0xffffffffu, s1, 1);
        s2 += __shfl_xor_sync(0xffffffffu, s2, 1);
        float mean = s1 * (1.0f / 128.0f);
        float var  = s2 * (1.0f / 128.0f) - mean * mean;
        float rs   = rsqrtf(var + EPSLN);
        size_t rowoff = ((size_t)(mbase + r)) << 7;
#pragma unroll
        for (int j = 0; j < 64; j += 4) {
            int cc = h64 + j;
            float4 v  = *(float4*)&ob[r * PA + cc];
            float4 xr = *(const float4*)(io + rowoff + cc);
            float4 gg = *(const float4*)(g2v + cc);
            float4 bb = *(const float4*)(be2v + cc);
            float4 o;
            o.x = xr.x + (v.x - mean) * rs * gg.x + bb.x;
            o.y = xr.y + (v.y - mean) * rs * gg.y + bb.y;
            o.z = xr.z + (v.z - mean) * rs * gg.z + bb.z;
            o.w = xr.w + (v.w - mean) * rs * gg.w + bb.w;
            *(float4*)(io + rowoff + cc) = o;
        }
    }
}

// ============================================================
extern "C" void kernel_launch(void* const* d_in, const int* in_sizes, int n_in,
                              void* d_out, int out_size) {
    const float* x          = (const float*)d_in[0];
    const float* w_qkv      = (const float*)d_in[1];
    const float* b_qkv      = (const float*)d_in[2];
    const float* bias_table = (const float*)d_in[3];
    const float* w_proj     = (const float*)d_in[4];
    const float* b_proj     = (const float*)d_in[5];
    const float* g1         = (const float*)d_in[6];
    const float* be1        = (const float*)d_in[7];
    const float* w_fc1      = (const float*)d_in[8];
    const float* b_fc1      = (const float*)d_in[9];
    const float* w_fc2      = (const float*)d_in[10];
    const float* b_fc2      = (const float*)d_in[11];
    const float* g2         = (const float*)d_in[12];
    const float* be2        = (const float*)d_in[13];
    const int*   rel_index  = (const int*)d_in[14];
    const float* attn_mask  = (const float*)d_in[15];
    float* out = (float*)d_out;

    cudaFuncSetAttribute(qkv_mma_kernel, cudaFuncAttributeMaxDynamicSharedMemorySize,
                         GEMM_SMEM_BYTES);
    cudaFuncSetAttribute(attn_mma_kernel, cudaFuncAttributeMaxDynamicSharedMemorySize,
                         ATT_SMEM_BYTES);
    cudaFuncSetAttribute(proj_mma_kernel, cudaFuncAttributeMaxDynamicSharedMemorySize,
                         GEMM_SMEM_BYTES);
    cudaFuncSetAttribute(mlp_mma_kernel, cudaFuncAttributeMaxDynamicSharedMemorySize,
                         MLP_SMEM_BYTES);

    qkv_mma_kernel<<<dim3(3, M_TOTAL / 64), 256, GEMM_SMEM_BYTES>>>(x, w_qkv, b_qkv);
    pb_kernel<<<dim3(256, NHEADS), 256>>>(bias_table, rel_index, attn_mask);
    attn_mma_kernel<<<M_TOTAL / 128, 256, ATT_SMEM_BYTES>>>();
    proj_mma_kernel<<<M_TOTAL / 64, 256, GEMM_SMEM_BYTES>>>(x, w_proj, b_proj, g1, be1, out);
    mlp_mma_kernel<<<M_TOTAL / 128, 256, MLP_SMEM_BYTES>>>(
        w_fc1, b_fc1, w_fc2, b_fc2, g2, be2, out);
}